// round 3
// baseline (speedup 1.0000x reference)
#include <cuda_runtime.h>
#include <cstdint>
#include <cstring>

// ============================================================================
// Sparse masked CNN pyramid (14 levels) + MLP head — round 3.
//   prep_weights : duplicate conv weights into (w,w) pair layout (once/launch)
//   build_all0   : levels 0..7 index maps + compaction (256 blocks)
//   build_top    : levels 8..13 (1 block)
//   conv1        : 5x5, cin=1 -> 32 at active pixels
//   convk        : 3x3 s2 32->32 sparse tile-GEMM, double-buffered taps, FFMA2
//   tail         : levels 8..13 convs + pools + MLP (1 block)
// ============================================================================

#define CAP 131072
#define NLEV 14
#define IDX_TOTAL 5592407

__device__ __align__(16) float g_FA[CAP * 32];
__device__ __align__(16) float g_FB[CAP * 32];
__device__ __align__(16) float g_Wdup[13 * 9 * 2048];   // [lvl][tap][ci][ch dup pairs]
__device__ int   g_idx[IDX_TOTAL];
__device__ int   g_pos[NLEV * CAP];
__device__ int   g_cnt[NLEV];
__device__ float g_pools[NLEV * 32];

__constant__ int c_LS[NLEV]   = {2048,1024,512,256,128,64,32,16,8,4,2,1,1,1};
__constant__ int c_IOFS[NLEV] = {0,4194304,5242880,5505024,5570560,5586944,5591040,
                                 5592064,5592320,5592384,5592400,5592404,5592405,5592406};

#define FMA2(d, a, b, c) \
    asm("fma.rn.f32x2 %0, %1, %2, %3;" : "=l"(d) : "l"(a), "l"(b), "l"(c))

__device__ __forceinline__ float2 upk(unsigned long long a) {
    float2 f; memcpy(&f, &a, 8); return f;
}

// ---- weight duplication: ws[lvl][tap][ci][ch] -> g_Wdup[...][ci][ch*2(+1)] --
__global__ void prep_weights(const float* __restrict__ ws) {
    int t = blockIdx.x * 256 + threadIdx.x;
    if (t < 13 * 9 * 32 * 32) {
        float w = ws[t];
        int ch = t & 31, rest = t >> 5;
        g_Wdup[rest * 64 + ch * 2]     = w;
        g_Wdup[rest * 64 + ch * 2 + 1] = w;
    }
}

// ---- block compaction step (1024-thread blocks only) ------------------------
__device__ __forceinline__ void emit(int level, bool act, int lin, int posword,
                                     int iofs, unsigned* bitdst) {
    __shared__ int ewcnt[32];
    __shared__ int ewbase[32];
    __shared__ int ebbase;
    int tid = threadIdx.x, wid = tid >> 5, lane = tid & 31;
    unsigned m = __ballot_sync(0xffffffffu, act);
    if (lane == 0) {
        ewcnt[wid] = __popc(m);
        if (bitdst) bitdst[wid] = m;
    }
    __syncthreads();
    if (tid < 32) {
        int cc = ewcnt[tid];
        int x = cc;
        #pragma unroll
        for (int o = 1; o < 32; o <<= 1) {
            int y = __shfl_up_sync(0xffffffffu, x, o);
            if (tid >= o) x += y;
        }
        ewbase[tid] = x - cc;
        if (tid == 31) ebbase = atomicAdd(&g_cnt[level], x);
    }
    __syncthreads();
    int idx = -1;
    if (act) {
        idx = ebbase + ewbase[wid] + __popc(m & ((1u << lane) - 1u));
        if (idx < CAP) g_pos[level * CAP + idx] = posword;
        else idx = -1;
    }
    if (lin >= 0) g_idx[iofs + lin] = idx;
    __syncthreads();
}

__device__ __forceinline__ int getbit(const unsigned* a, int c) {
    return (a[c >> 5] >> (c & 31)) & 1;
}

// ---- levels 0..7, block = 128x128 base tile ---------------------------------
__global__ __launch_bounds__(1024) void build_all0(const float* __restrict__ mask) {
    __shared__ unsigned a0[512];
    __shared__ unsigned a1[128];
    __shared__ unsigned a2[32];
    __shared__ unsigned a3[8];
    __shared__ unsigned a4[32];
    __shared__ unsigned a5[32];
    __shared__ unsigned a6[32];
    int tid = threadIdx.x;
    int tx = blockIdx.x & 15, ty = blockIdx.x >> 4;

    for (int r = 0; r < 16; r++) {
        int c = r * 1024 + tid;
        int li = c >> 7, lj = c & 127;
        int i = ty * 128 + li, j = tx * 128 + lj;
        bool act = (mask[i * 2048 + j] != 0.0f);
        emit(0, act, i * 2048 + j, (i << 16) | j, c_IOFS[0], a0 + r * 32);
    }
    unsigned* bits[8] = {a0, a1, a2, a3, a4, a5, a6, nullptr};
    #pragma unroll
    for (int L = 1; L <= 7; L++) {
        int t = 128 >> L;
        int cells = t * t;
        int chunks = (cells + 1023) >> 10;
        int tprev = t * 2;
        for (int r = 0; r < chunks; r++) {
            int c = r * 1024 + tid;
            bool act = false;
            int lin = -1, pw = 0;
            if (c < cells) {
                int li = c / t, lj = c - li * t;
                int c00 = (2 * li) * tprev + 2 * lj;
                const unsigned* pb = bits[L - 1];
                act = getbit(pb, c00) | getbit(pb, c00 + 1) |
                      getbit(pb, c00 + tprev) | getbit(pb, c00 + tprev + 1);
                int i = ty * t + li, j = tx * t + lj;
                lin = i * (2048 >> L) + j;
                pw = (i << 16) | j;
            }
            emit(L, act, lin, pw, c_IOFS[L], (L < 7) ? (bits[L] + r * 32) : nullptr);
        }
    }
}

// ---- levels 8..13, single block ----------------------------------------------
__global__ __launch_bounds__(1024) void build_top() {
    int tid = threadIdx.x;
    for (int k = 8; k < NLEV; k++) {
        int s = c_LS[k], sp = c_LS[k - 1];
        int cells = s * s;
        const int* Ip = g_idx + c_IOFS[k - 1];
        bool act = false;
        int lin = -1, pw = 0;
        if (tid < cells) {
            int i = tid / s, j = tid - i * s;
            #pragma unroll
            for (int di = 0; di < 2; di++)
                #pragma unroll
                for (int dj = 0; dj < 2; dj++) {
                    int r = 2 * i + di, cc = 2 * j + dj;
                    if (r < sp && cc < sp && Ip[r * sp + cc] >= 0) act = true;
                }
            lin = tid;
            pw = (i << 16) | j;
        }
        emit(k, act, lin, pw, c_IOFS[k], nullptr);
    }
}

// ---- level-0 conv: 5x5, cin=1 -> 32 ------------------------------------------
__global__ void conv1_kernel(const float* __restrict__ x, const float* __restrict__ w1) {
    __shared__ float sw[800];
    __shared__ float bsum[32];
    int tid = threadIdx.x;
    for (int t = tid; t < 800; t += 256) sw[t] = w1[t];
    if (tid < 32) bsum[tid] = 0.f;
    __syncthreads();

    int n = min(g_cnt[0], CAP);
    int lane = tid & 31;
    int gw = (blockIdx.x * 256 + tid) >> 5;
    int nw = (gridDim.x * 256) >> 5;
    float pool = 0.f;
    for (int p = gw; p < n; p += nw) {
        int pw = g_pos[p];
        int i = pw >> 16, j = pw & 0xffff;
        float acc = 0.f;
        #pragma unroll
        for (int dy = 0; dy < 5; dy++) {
            int r = i + dy - 2;
            if ((unsigned)r < 2048u) {
                #pragma unroll
                for (int dx = 0; dx < 5; dx++) {
                    int cc = j + dx - 2;
                    if ((unsigned)cc < 2048u)
                        acc = fmaf(x[r * 2048 + cc], sw[(dy * 5 + dx) * 32 + lane], acc);
                }
            }
        }
        acc = fmaxf(acc, 0.f);
        g_FA[(size_t)p * 32 + lane] = acc;
        pool += acc;
    }
    atomicAdd(&bsum[lane], pool);
    __syncthreads();
    if (tid < 32) atomicAdd(&g_pools[tid], bsum[tid]);
}

// ---- convk helpers -----------------------------------------------------------
__device__ __forceinline__ void gather_tap(const float* __restrict__ Fprev,
                                           const int* __restrict__ sNbr, int d,
                                           float* __restrict__ sAb,
                                           float* __restrict__ sWb,
                                           const float* __restrict__ wtap, int tid) {
    // weights: 2048 floats (pre-duplicated pairs)
    {
        const float4* w4 = (const float4*)wtap;
        float4* wd = (float4*)sWb;
        wd[tid] = w4[tid];
        wd[tid + 256] = w4[tid + 256];
    }
    // rows: 2 threads per row, 16 channels each
    int row = tid >> 1;
    int cb = (tid & 1) * 16;
    int nb = sNbr[d * 128 + row];
    if (nb >= 0) {
        const float4* src = (const float4*)(Fprev + (size_t)nb * 32 + cb);
        #pragma unroll
        for (int q = 0; q < 4; q++) {
            float4 v = src[q];
            int ci = cb + q * 4;
            sAb[(ci + 0) * 128 + row] = v.x;
            sAb[(ci + 1) * 128 + row] = v.y;
            sAb[(ci + 2) * 128 + row] = v.z;
            sAb[(ci + 3) * 128 + row] = v.w;
        }
    } else {
        #pragma unroll
        for (int q = 0; q < 16; q++) sAb[(cb + q) * 128 + row] = 0.f;
    }
}

__device__ __forceinline__ void gemm_tap(const float* __restrict__ sAb,
                                         const float* __restrict__ sWb,
                                         int pb, int ch, unsigned long long acc[8]) {
    #pragma unroll
    for (int ci = 0; ci < 32; ci++) {
        ulonglong2 v  = *(const ulonglong2*)(sAb + ci * 128 + pb);
        ulonglong2 wa = *(const ulonglong2*)(sWb + ci * 64 + ch * 2);
        ulonglong2 wb = *(const ulonglong2*)(sWb + ci * 64 + ch * 2 + 4);
        FMA2(acc[0], v.x, wa.x, acc[0]);
        FMA2(acc[1], v.x, wa.y, acc[1]);
        FMA2(acc[2], v.x, wb.x, acc[2]);
        FMA2(acc[3], v.x, wb.y, acc[3]);
        FMA2(acc[4], v.y, wa.x, acc[4]);
        FMA2(acc[5], v.y, wa.y, acc[5]);
        FMA2(acc[6], v.y, wb.x, acc[6]);
        FMA2(acc[7], v.y, wb.y, acc[7]);
    }
}

// smem: sA[2][4096] + sW[2][2048] + sNbr[9*128] + spool[32] + swm[4]
#define CONVK_SMEM ((2 * 4096 + 2 * 2048 + 32) * 4 + (9 * 128 + 4) * 4)

__global__ __launch_bounds__(256, 4) void convk_kernel(int level, int sprev,
                                                       int iofs_prev) {
    extern __shared__ float smem[];
    float* sA0 = smem;
    float* sA1 = smem + 4096;
    float* sW0 = smem + 8192;
    float* sW1 = smem + 10240;
    int*   sNbr = (int*)(smem + 12288);
    float* spool = (float*)(sNbr + 9 * 128);
    unsigned* swm = (unsigned*)(spool + 32);

    const float* Fprev;
    float* Fcur;
    if (level & 1) { Fprev = g_FA; Fcur = g_FB; }
    else           { Fprev = g_FB; Fcur = g_FA; }
    const float* wlvl = g_Wdup + (size_t)(level - 1) * 9 * 2048;

    int tid = threadIdx.x;
    if (tid < 32) spool[tid] = 0.f;

    int n = min(g_cnt[level], CAP);
    const int* posl = g_pos + level * CAP;
    const int* Iprev = g_idx + iofs_prev;

    int ch = (tid & 7) * 4;       // 4 output channels
    int pb = (tid >> 3) * 4;      // 4 consecutive positions
    float pl0 = 0.f, pl1 = 0.f, pl2 = 0.f, pl3 = 0.f;

    for (int base = blockIdx.x * 128; base < n; base += gridDim.x * 128) {
        __syncthreads();          // previous tile fully consumed
        // ---- neighbor indices + per-tile tap mask ----
        unsigned tb = 0;
        if (tid < 128) {
            int p = base + tid;
            if (p < n) {
                int pw = posl[p];
                int pi = pw >> 16, pj = pw & 0xffff;
                #pragma unroll
                for (int d = 0; d < 9; d++) {
                    int r = 2 * pi + d / 3 - 1;
                    int cc = 2 * pj + d % 3 - 1;
                    int nb = -1;
                    if ((unsigned)r < (unsigned)sprev && (unsigned)cc < (unsigned)sprev)
                        nb = Iprev[r * sprev + cc];
                    sNbr[d * 128 + tid] = nb;
                    tb |= (nb >= 0 ? 1u : 0u) << d;
                }
            } else {
                #pragma unroll
                for (int d = 0; d < 9; d++) sNbr[d * 128 + tid] = -1;
            }
        }
        unsigned wm = __reduce_or_sync(0xffffffffu, tb);
        if ((tid & 31) == 0) swm[tid >> 5] = (tid < 128) ? wm : 0u;
        __syncthreads();
        unsigned mask = swm[0] | swm[1] | swm[2] | swm[3];

        unsigned long long acc[8] = {0ull,0ull,0ull,0ull,0ull,0ull,0ull,0ull};
        int m = (int)mask;
        int f = __ffs(m) - 1; m &= m - 1;
        gather_tap(Fprev, sNbr, f, sA0, sW0, wlvl + f * 2048, tid);
        __syncthreads();
        int cur = 0;   // buffer holding the tap ready to compute
        while (m) {
            int t = __ffs(m) - 1; m &= m - 1;
            gather_tap(Fprev, sNbr, t, cur ? sA0 : sA1, cur ? sW0 : sW1,
                       wlvl + t * 2048, tid);
            gemm_tap(cur ? sA1 : sA0, cur ? sW1 : sW0, pb, ch, acc);
            __syncthreads();
            cur ^= 1;
        }
        gemm_tap(cur ? sA1 : sA0, cur ? sW1 : sW0, pb, ch, acc);

        // ---- epilogue: relu, store, pool ----
        float2 a0 = upk(acc[0]), a1 = upk(acc[1]), a2 = upk(acc[2]), a3 = upk(acc[3]);
        float2 b0 = upk(acc[4]), b1 = upk(acc[5]), b2 = upk(acc[6]), b3 = upk(acc[7]);
        float4 vq[4];
        vq[0] = make_float4(a0.x, a1.x, a2.x, a3.x);
        vq[1] = make_float4(a0.y, a1.y, a2.y, a3.y);
        vq[2] = make_float4(b0.x, b1.x, b2.x, b3.x);
        vq[3] = make_float4(b0.y, b1.y, b2.y, b3.y);
        #pragma unroll
        for (int q = 0; q < 4; q++) {
            int p = base + pb + q;
            if (p < n) {
                float4 v;
                v.x = fmaxf(vq[q].x, 0.f);
                v.y = fmaxf(vq[q].y, 0.f);
                v.z = fmaxf(vq[q].z, 0.f);
                v.w = fmaxf(vq[q].w, 0.f);
                *(float4*)(Fcur + (size_t)p * 32 + ch) = v;
                pl0 += v.x; pl1 += v.y; pl2 += v.z; pl3 += v.w;
            }
        }
    }
    pl0 += __shfl_xor_sync(0xffffffffu, pl0, 8); pl0 += __shfl_xor_sync(0xffffffffu, pl0, 16);
    pl1 += __shfl_xor_sync(0xffffffffu, pl1, 8); pl1 += __shfl_xor_sync(0xffffffffu, pl1, 16);
    pl2 += __shfl_xor_sync(0xffffffffu, pl2, 8); pl2 += __shfl_xor_sync(0xffffffffu, pl2, 16);
    pl3 += __shfl_xor_sync(0xffffffffu, pl3, 8); pl3 += __shfl_xor_sync(0xffffffffu, pl3, 16);
    __syncthreads();
    if ((tid & 31) < 8) {
        atomicAdd(&spool[ch + 0], pl0);
        atomicAdd(&spool[ch + 1], pl1);
        atomicAdd(&spool[ch + 2], pl2);
        atomicAdd(&spool[ch + 3], pl3);
    }
    __syncthreads();
    if (tid < 32) atomicAdd(&g_pools[level * 32 + tid], spool[tid]);
}

// ---- tail: levels 8..13 convs + pools + MLP, single block --------------------
__global__ __launch_bounds__(256) void tail_kernel(
    const float* __restrict__ ws,
    const float* __restrict__ wm1, const float* __restrict__ bm1,
    const float* __restrict__ wm2, const float* __restrict__ bm2,
    float* __restrict__ out) {
    __shared__ float spool[32];
    int tid = threadIdx.x, wid = tid >> 5, lane = tid & 31;

    for (int k = 8; k < NLEV; k++) {
        int n = min(g_cnt[k], CAP);
        int sp = c_LS[k - 1];
        const int* Ip = g_idx + c_IOFS[k - 1];
        const float* Fp = (k & 1) ? g_FA : g_FB;
        float* Fc = (k & 1) ? g_FB : g_FA;
        const float* W = ws + (size_t)(k - 1) * 9216;
        if (tid < 32) spool[tid] = 0.f;
        __syncthreads();
        float pool = 0.f;
        for (int p = wid; p < n; p += 8) {
            int pw = g_pos[k * CAP + p];
            int pi = pw >> 16, pj = pw & 0xffff;
            float acc = 0.f;
            for (int d = 0; d < 9; d++) {
                int r = 2 * pi + d / 3 - 1;
                int cc = 2 * pj + d % 3 - 1;
                if ((unsigned)r < (unsigned)sp && (unsigned)cc < (unsigned)sp) {
                    int nb = Ip[r * sp + cc];
                    if (nb >= 0) {
                        float row = Fp[(size_t)nb * 32 + lane];
                        const float* wd = W + d * 1024;
                        #pragma unroll
                        for (int ci = 0; ci < 32; ci++)
                            acc = fmaf(__shfl_sync(0xffffffffu, row, ci),
                                       wd[ci * 32 + lane], acc);
                    }
                }
            }
            acc = fmaxf(acc, 0.f);
            Fc[(size_t)p * 32 + lane] = acc;
            pool += acc;
        }
        atomicAdd(&spool[lane], pool);
        __syncthreads();
        if (tid < 32) g_pools[k * 32 + tid] = spool[tid];
        __syncthreads();
    }

    __shared__ float sf[448];
    __shared__ float sh[256];
    for (int i = tid; i < 448; i += 256) {
        int k = i >> 5;
        float cnt = (float)max(g_cnt[k], 1);
        sf[i] = g_pools[i] / cnt;
    }
    __syncthreads();
    {
        float acc = bm1[tid];
        #pragma unroll 4
        for (int i = 0; i < 448; i++) acc = fmaf(sf[i], wm1[i * 256 + tid], acc);
        sh[tid] = fmaxf(acc, 0.f);
    }
    __syncthreads();
    if (tid < 128) {
        float acc = bm2[tid];
        #pragma unroll 4
        for (int j = 0; j < 256; j++) acc = fmaf(sh[j], wm2[j * 128 + tid], acc);
        out[tid] = acc;
    }
}

// ---- host launch ---------------------------------------------------------------
static const int H_LS[NLEV]   = {2048,1024,512,256,128,64,32,16,8,4,2,1,1,1};
static const int H_IOFS[NLEV] = {0,4194304,5242880,5505024,5570560,5586944,5591040,
                                 5592064,5592320,5592384,5592400,5592404,5592405,5592406};

extern "C" void kernel_launch(void* const* d_in, const int* in_sizes, int n_in,
                              void* d_out, int out_size) {
    const float* x    = (const float*)d_in[0];
    const float* mask = (const float*)d_in[1];
    const float* w1   = (const float*)d_in[2];
    const float* ws   = (const float*)d_in[3];
    const float* wm1  = (const float*)d_in[4];
    const float* bm1  = (const float*)d_in[5];
    const float* wm2  = (const float*)d_in[6];
    const float* bm2  = (const float*)d_in[7];
    float* out = (float*)d_out;

    cudaFuncSetAttribute((const void*)convk_kernel,
                         cudaFuncAttributeMaxDynamicSharedMemorySize, CONVK_SMEM);

    void* cnt_ptr = nullptr;
    void* pools_ptr = nullptr;
    cudaGetSymbolAddress(&cnt_ptr, g_cnt);
    cudaGetSymbolAddress(&pools_ptr, g_pools);
    cudaMemsetAsync(cnt_ptr, 0, NLEV * sizeof(int));
    cudaMemsetAsync(pools_ptr, 0, NLEV * 32 * sizeof(float));

    prep_weights<<<468, 256>>>(ws);
    build_all0<<<256, 1024>>>(mask);
    build_top<<<1, 1024>>>();

    conv1_kernel<<<2048, 256>>>(x, w1);

    static const int cgrid[8] = {0, 592, 592, 592, 128, 32, 8, 2};
    for (int k = 1; k <= 7; k++)
        convk_kernel<<<cgrid[k], 256, CONVK_SMEM>>>(k, H_LS[k - 1], H_IOFS[k - 1]);

    tail_kernel<<<1, 256>>>(ws, wm1, bm1, wm2, bm2, out);
}

// round 4
// speedup vs baseline: 1.0072x; 1.0072x over previous
#include <cuda_runtime.h>
#include <cstdint>
#include <cstring>

// ============================================================================
// Sparse masked CNN pyramid (14 levels) + MLP head — round 4.
//   prep_weights : dup conv weights into (w,w) pairs + zero counters/pools
//   build_all0   : levels 0..7 index maps + compaction (256 blocks)
//   build_top    : levels 8..13 (1 block)
//   conv1        : 5x5, cin=1 -> 32 at active pixels
//   convk        : 3x3 s2 32->32 sparse tile-GEMM, FFMA2, weights once/block
//   tail         : levels 8..13 convs + pools + MLP (1 block)
// ============================================================================

#define CAP 131072
#define NLEV 14
#define IDX_TOTAL 5592407

__device__ __align__(16) float g_FA[CAP * 32];
__device__ __align__(16) float g_FB[CAP * 32];
__device__ __align__(16) float g_Wdup[13 * 9 * 2048];   // [lvl][tap][ci][ch pairs]
__device__ int   g_idx[IDX_TOTAL];
__device__ int   g_pos[NLEV * CAP];
__device__ int   g_cnt[NLEV];
__device__ float g_pools[NLEV * 32];

__constant__ int c_LS[NLEV]   = {2048,1024,512,256,128,64,32,16,8,4,2,1,1,1};
__constant__ int c_IOFS[NLEV] = {0,4194304,5242880,5505024,5570560,5586944,5591040,
                                 5592064,5592320,5592384,5592400,5592404,5592405,5592406};

#define FMA2(d, a, b, c) \
    asm("fma.rn.f32x2 %0, %1, %2, %3;" : "=l"(d) : "l"(a), "l"(b), "l"(c))

__device__ __forceinline__ float2 upk(unsigned long long a) {
    float2 f; memcpy(&f, &a, 8); return f;
}

// ---- weight dup + zero init -------------------------------------------------
__global__ __launch_bounds__(512) void prep_weights(const float* __restrict__ ws) {
    int t = blockIdx.x * 512 + threadIdx.x;
    if (blockIdx.x == 0) {
        if (threadIdx.x < NLEV) g_cnt[threadIdx.x] = 0;
        if (threadIdx.x < NLEV * 32) g_pools[threadIdx.x] = 0.f;
    }
    if (t < 13 * 9 * 32 * 32) {
        float w = ws[t];
        int ch = t & 31, rest = t >> 5;
        g_Wdup[rest * 64 + ch * 2]     = w;
        g_Wdup[rest * 64 + ch * 2 + 1] = w;
    }
}

// ---- block compaction step (1024-thread blocks only) -------------------------
__device__ __forceinline__ void emit(int level, bool act, int lin, int posword,
                                     int iofs, unsigned* bitdst) {
    __shared__ int ewcnt[32];
    __shared__ int ewbase[32];
    __shared__ int ebbase;
    int tid = threadIdx.x, wid = tid >> 5, lane = tid & 31;
    unsigned m = __ballot_sync(0xffffffffu, act);
    if (lane == 0) {
        ewcnt[wid] = __popc(m);
        if (bitdst) bitdst[wid] = m;
    }
    __syncthreads();
    if (tid < 32) {
        int cc = ewcnt[tid];
        int x = cc;
        #pragma unroll
        for (int o = 1; o < 32; o <<= 1) {
            int y = __shfl_up_sync(0xffffffffu, x, o);
            if (tid >= o) x += y;
        }
        ewbase[tid] = x - cc;
        if (tid == 31) ebbase = atomicAdd(&g_cnt[level], x);
    }
    __syncthreads();
    int idx = -1;
    if (act) {
        idx = ebbase + ewbase[wid] + __popc(m & ((1u << lane) - 1u));
        if (idx < CAP) g_pos[level * CAP + idx] = posword;
        else idx = -1;
    }
    if (lin >= 0) g_idx[iofs + lin] = idx;
    __syncthreads();
}

__device__ __forceinline__ int getbit(const unsigned* a, int c) {
    return (a[c >> 5] >> (c & 31)) & 1;
}

// ---- levels 0..7, block = 128x128 base tile -----------------------------------
__global__ __launch_bounds__(1024) void build_all0(const float* __restrict__ mask) {
    __shared__ unsigned a0[512];
    __shared__ unsigned a1[128];
    __shared__ unsigned a2[32];
    __shared__ unsigned a3[8];
    __shared__ unsigned a4[32];
    __shared__ unsigned a5[32];
    __shared__ unsigned a6[32];
    int tid = threadIdx.x;
    int tx = blockIdx.x & 15, ty = blockIdx.x >> 4;

    for (int r = 0; r < 16; r++) {
        int c = r * 1024 + tid;
        int li = c >> 7, lj = c & 127;
        int i = ty * 128 + li, j = tx * 128 + lj;
        bool act = (mask[i * 2048 + j] != 0.0f);
        emit(0, act, i * 2048 + j, (i << 16) | j, c_IOFS[0], a0 + r * 32);
    }
    unsigned* bits[8] = {a0, a1, a2, a3, a4, a5, a6, nullptr};
    #pragma unroll
    for (int L = 1; L <= 7; L++) {
        int t = 128 >> L;
        int cells = t * t;
        int chunks = (cells + 1023) >> 10;
        int tprev = t * 2;
        for (int r = 0; r < chunks; r++) {
            int c = r * 1024 + tid;
            bool act = false;
            int lin = -1, pw = 0;
            if (c < cells) {
                int li = c / t, lj = c - li * t;
                int c00 = (2 * li) * tprev + 2 * lj;
                const unsigned* pb = bits[L - 1];
                act = getbit(pb, c00) | getbit(pb, c00 + 1) |
                      getbit(pb, c00 + tprev) | getbit(pb, c00 + tprev + 1);
                int i = ty * t + li, j = tx * t + lj;
                lin = i * (2048 >> L) + j;
                pw = (i << 16) | j;
            }
            emit(L, act, lin, pw, c_IOFS[L], (L < 7) ? (bits[L] + r * 32) : nullptr);
        }
    }
}

// ---- levels 8..13, single block -------------------------------------------------
__global__ __launch_bounds__(1024) void build_top() {
    int tid = threadIdx.x;
    for (int k = 8; k < NLEV; k++) {
        int s = c_LS[k], sp = c_LS[k - 1];
        int cells = s * s;
        const int* Ip = g_idx + c_IOFS[k - 1];
        bool act = false;
        int lin = -1, pw = 0;
        if (tid < cells) {
            int i = tid / s, j = tid - i * s;
            #pragma unroll
            for (int di = 0; di < 2; di++)
                #pragma unroll
                for (int dj = 0; dj < 2; dj++) {
                    int r = 2 * i + di, cc = 2 * j + dj;
                    if (r < sp && cc < sp && Ip[r * sp + cc] >= 0) act = true;
                }
            lin = tid;
            pw = (i << 16) | j;
        }
        emit(k, act, lin, pw, c_IOFS[k], nullptr);
    }
}

// ---- level-0 conv: 5x5, cin=1 -> 32 ---------------------------------------------
__global__ void conv1_kernel(const float* __restrict__ x, const float* __restrict__ w1) {
    __shared__ float sw[800];
    __shared__ float bsum[32];
    int tid = threadIdx.x;
    for (int t = tid; t < 800; t += 256) sw[t] = w1[t];
    if (tid < 32) bsum[tid] = 0.f;
    __syncthreads();

    int n = min(g_cnt[0], CAP);
    int lane = tid & 31;
    int gw = (blockIdx.x * 256 + tid) >> 5;
    int nw = (gridDim.x * 256) >> 5;
    float pool = 0.f;
    for (int p = gw; p < n; p += nw) {
        int pw = g_pos[p];
        int i = pw >> 16, j = pw & 0xffff;
        float acc = 0.f;
        #pragma unroll
        for (int dy = 0; dy < 5; dy++) {
            int r = i + dy - 2;
            if ((unsigned)r < 2048u) {
                #pragma unroll
                for (int dx = 0; dx < 5; dx++) {
                    int cc = j + dx - 2;
                    if ((unsigned)cc < 2048u)
                        acc = fmaf(x[r * 2048 + cc], sw[(dy * 5 + dx) * 32 + lane], acc);
                }
            }
        }
        acc = fmaxf(acc, 0.f);
        g_FA[(size_t)p * 32 + lane] = acc;
        pool += acc;
    }
    atomicAdd(&bsum[lane], pool);
    __syncthreads();
    if (tid < 32) atomicAdd(&g_pools[tid], bsum[tid]);
}

// ---- levels 1..7: sparse tile-GEMM (128 pos x 32 ch), FFMA2 --------------------
// smem: sW 18432 f (dup pairs, once/block) | sA 32*132 f | sNbr 9*128 i | spool 32 f
#define SA_STRIDE 132
#define CONVK_SMEM (18432 * 4 + 32 * SA_STRIDE * 4 + 9 * 128 * 4 + 32 * 4)

__global__ __launch_bounds__(256) void convk_kernel(int level, int sprev,
                                                    int iofs_prev) {
    extern __shared__ float smem[];
    float* sW   = smem;                                  // [9][32][64] dup pairs
    float* sA   = smem + 18432;                          // [32][SA_STRIDE]
    int*   sNbr = (int*)(smem + 18432 + 32 * SA_STRIDE); // [9][128]
    float* spool = (float*)(sNbr + 9 * 128);             // [32]

    const float* Fprev;
    float* Fcur;
    if (level & 1) { Fprev = g_FA; Fcur = g_FB; }
    else           { Fprev = g_FB; Fcur = g_FA; }

    int tid = threadIdx.x;
    // stage duplicated weights for this level ONCE per block (72KB)
    {
        const float4* src = (const float4*)(g_Wdup + (size_t)(level - 1) * 18432);
        float4* dst = (float4*)sW;
        #pragma unroll
        for (int t = 0; t < 18; t++) dst[tid + t * 256] = src[tid + t * 256];
    }
    if (tid < 32) spool[tid] = 0.f;
    __syncthreads();

    int n = min(g_cnt[level], CAP);
    const int* posl = g_pos + level * CAP;
    const int* Iprev = g_idx + iofs_prev;

    int ch = (tid & 7) * 4;       // 4 output channels
    int pg = tid >> 3;            // position group 0..31 (4 positions each)
    float pl0 = 0.f, pl1 = 0.f, pl2 = 0.f, pl3 = 0.f;

    for (int base = blockIdx.x * 128; base < n; base += gridDim.x * 128) {
        __syncthreads();          // previous tile fully consumed
        if (tid < 128) {
            int p = base + tid;
            if (p < n) {
                int pw = posl[p];
                int pi = pw >> 16, pj = pw & 0xffff;
                #pragma unroll
                for (int d = 0; d < 9; d++) {
                    int r = 2 * pi + d / 3 - 1;
                    int cc = 2 * pj + d % 3 - 1;
                    int nb = -1;
                    if ((unsigned)r < (unsigned)sprev && (unsigned)cc < (unsigned)sprev)
                        nb = Iprev[r * sprev + cc];
                    sNbr[d * 128 + tid] = nb;
                }
            } else {
                #pragma unroll
                for (int d = 0; d < 9; d++) sNbr[d * 128 + tid] = -1;
            }
        }
        __syncthreads();

        unsigned long long acc[8] = {0ull,0ull,0ull,0ull,0ull,0ull,0ull,0ull};

        #pragma unroll 1
        for (int d = 0; d < 9; d++) {
            // gather 128 rows into sA[ci][row] (2 threads/row, 16 ch each)
            {
                int row = tid >> 1;
                int cb = (tid & 1) * 16;
                int nb = sNbr[d * 128 + row];
                if (nb >= 0) {
                    const float4* src = (const float4*)(Fprev + (size_t)nb * 32 + cb);
                    #pragma unroll
                    for (int q = 0; q < 4; q++) {
                        float4 v = src[q];
                        int ci = cb + q * 4;
                        sA[(ci + 0) * SA_STRIDE + row] = v.x;
                        sA[(ci + 1) * SA_STRIDE + row] = v.y;
                        sA[(ci + 2) * SA_STRIDE + row] = v.z;
                        sA[(ci + 3) * SA_STRIDE + row] = v.w;
                    }
                } else {
                    #pragma unroll
                    for (int q = 0; q < 16; q++) sA[(cb + q) * SA_STRIDE + row] = 0.f;
                }
            }
            __syncthreads();
            // GEMM: per ci: 1 LDS.128 (4 pos = 2 pairs) + 2 LDS.128 (w pairs) + 8 FMA2
            const float* wd = sW + d * 2048;
            #pragma unroll
            for (int ci = 0; ci < 32; ci++) {
                ulonglong2 v  = *(const ulonglong2*)(sA + ci * SA_STRIDE + pg * 4);
                ulonglong2 wa = *(const ulonglong2*)(wd + ci * 64 + ch * 2);
                ulonglong2 wb = *(const ulonglong2*)(wd + ci * 64 + ch * 2 + 4);
                FMA2(acc[0], v.x, wa.x, acc[0]);
                FMA2(acc[1], v.x, wa.y, acc[1]);
                FMA2(acc[2], v.x, wb.x, acc[2]);
                FMA2(acc[3], v.x, wb.y, acc[3]);
                FMA2(acc[4], v.y, wa.x, acc[4]);
                FMA2(acc[5], v.y, wa.y, acc[5]);
                FMA2(acc[6], v.y, wb.x, acc[6]);
                FMA2(acc[7], v.y, wb.y, acc[7]);
            }
            __syncthreads();
        }

        // epilogue: relu, store, pool  (acc[j]=pos pair(0,1) ch+j; acc[4+j]=pair(2,3))
        float2 a0 = upk(acc[0]), a1 = upk(acc[1]), a2 = upk(acc[2]), a3 = upk(acc[3]);
        float2 b0 = upk(acc[4]), b1 = upk(acc[5]), b2 = upk(acc[6]), b3 = upk(acc[7]);
        float4 vq[4];
        vq[0] = make_float4(a0.x, a1.x, a2.x, a3.x);
        vq[1] = make_float4(a0.y, a1.y, a2.y, a3.y);
        vq[2] = make_float4(b0.x, b1.x, b2.x, b3.x);
        vq[3] = make_float4(b0.y, b1.y, b2.y, b3.y);
        #pragma unroll
        for (int q = 0; q < 4; q++) {
            int p = base + pg * 4 + q;
            if (p < n) {
                float4 v;
                v.x = fmaxf(vq[q].x, 0.f);
                v.y = fmaxf(vq[q].y, 0.f);
                v.z = fmaxf(vq[q].z, 0.f);
                v.w = fmaxf(vq[q].w, 0.f);
                *(float4*)(Fcur + (size_t)p * 32 + ch) = v;
                pl0 += v.x; pl1 += v.y; pl2 += v.z; pl3 += v.w;
            }
        }
    }
    pl0 += __shfl_xor_sync(0xffffffffu, pl0, 8); pl0 += __shfl_xor_sync(0xffffffffu, pl0, 16);
    pl1 += __shfl_xor_sync(0xffffffffu, pl1, 8); pl1 += __shfl_xor_sync(0xffffffffu, pl1, 16);
    pl2 += __shfl_xor_sync(0xffffffffu, pl2, 8); pl2 += __shfl_xor_sync(0xffffffffu, pl2, 16);
    pl3 += __shfl_xor_sync(0xffffffffu, pl3, 8); pl3 += __shfl_xor_sync(0xffffffffu, pl3, 16);
    __syncthreads();
    if ((tid & 31) < 8) {
        atomicAdd(&spool[ch + 0], pl0);
        atomicAdd(&spool[ch + 1], pl1);
        atomicAdd(&spool[ch + 2], pl2);
        atomicAdd(&spool[ch + 3], pl3);
    }
    __syncthreads();
    if (tid < 32) atomicAdd(&g_pools[level * 32 + tid], spool[tid]);
}

// ---- tail: levels 8..13 convs + pools + MLP, single block ------------------------
__global__ __launch_bounds__(256) void tail_kernel(
    const float* __restrict__ ws,
    const float* __restrict__ wm1, const float* __restrict__ bm1,
    const float* __restrict__ wm2, const float* __restrict__ bm2,
    float* __restrict__ out) {
    __shared__ float spool[32];
    int tid = threadIdx.x, wid = tid >> 5, lane = tid & 31;

    for (int k = 8; k < NLEV; k++) {
        int n = min(g_cnt[k], CAP);
        int sp = c_LS[k - 1];
        const int* Ip = g_idx + c_IOFS[k - 1];
        const float* Fp = (k & 1) ? g_FA : g_FB;
        float* Fc = (k & 1) ? g_FB : g_FA;
        const float* W = ws + (size_t)(k - 1) * 9216;
        if (tid < 32) spool[tid] = 0.f;
        __syncthreads();
        float pool = 0.f;
        for (int p = wid; p < n; p += 8) {
            int pw = g_pos[k * CAP + p];
            int pi = pw >> 16, pj = pw & 0xffff;
            float acc = 0.f;
            for (int d = 0; d < 9; d++) {
                int r = 2 * pi + d / 3 - 1;
                int cc = 2 * pj + d % 3 - 1;
                if ((unsigned)r < (unsigned)sp && (unsigned)cc < (unsigned)sp) {
                    int nb = Ip[r * sp + cc];
                    if (nb >= 0) {
                        float row = Fp[(size_t)nb * 32 + lane];
                        const float* wd = W + d * 1024;
                        #pragma unroll
                        for (int ci = 0; ci < 32; ci++)
                            acc = fmaf(__shfl_sync(0xffffffffu, row, ci),
                                       wd[ci * 32 + lane], acc);
                    }
                }
            }
            acc = fmaxf(acc, 0.f);
            Fc[(size_t)p * 32 + lane] = acc;
            pool += acc;
        }
        atomicAdd(&spool[lane], pool);
        __syncthreads();
        if (tid < 32) g_pools[k * 32 + tid] = spool[tid];
        __syncthreads();
    }

    __shared__ float sf[448];
    __shared__ float sh[256];
    for (int i = tid; i < 448; i += 256) {
        int k = i >> 5;
        float cnt = (float)max(g_cnt[k], 1);
        sf[i] = g_pools[i] / cnt;
    }
    __syncthreads();
    {
        float acc = bm1[tid];
        #pragma unroll 4
        for (int i = 0; i < 448; i++) acc = fmaf(sf[i], wm1[i * 256 + tid], acc);
        sh[tid] = fmaxf(acc, 0.f);
    }
    __syncthreads();
    if (tid < 128) {
        float acc = bm2[tid];
        #pragma unroll 4
        for (int j = 0; j < 256; j++) acc = fmaf(sh[j], wm2[j * 128 + tid], acc);
        out[tid] = acc;
    }
}

// ---- host launch ------------------------------------------------------------------
static const int H_LS[NLEV]   = {2048,1024,512,256,128,64,32,16,8,4,2,1,1,1};
static const int H_IOFS[NLEV] = {0,4194304,5242880,5505024,5570560,5586944,5591040,
                                 5592064,5592320,5592384,5592400,5592404,5592405,5592406};

extern "C" void kernel_launch(void* const* d_in, const int* in_sizes, int n_in,
                              void* d_out, int out_size) {
    const float* x    = (const float*)d_in[0];
    const float* mask = (const float*)d_in[1];
    const float* w1   = (const float*)d_in[2];
    const float* ws   = (const float*)d_in[3];
    const float* wm1  = (const float*)d_in[4];
    const float* bm1  = (const float*)d_in[5];
    const float* wm2  = (const float*)d_in[6];
    const float* bm2  = (const float*)d_in[7];
    float* out = (float*)d_out;

    cudaFuncSetAttribute((const void*)convk_kernel,
                         cudaFuncAttributeMaxDynamicSharedMemorySize, CONVK_SMEM);

    prep_weights<<<234, 512>>>(ws);
    build_all0<<<256, 1024>>>(mask);
    build_top<<<1, 1024>>>();

    conv1_kernel<<<2048, 256>>>(x, w1);

    static const int cgrid[8] = {0, 296, 296, 244, 124, 32, 8, 2};
    for (int k = 1; k <= 7; k++)
        convk_kernel<<<cgrid[k], 256, CONVK_SMEM>>>(k, H_LS[k - 1], H_IOFS[k - 1]);

    tail_kernel<<<1, 256>>>(ws, wm1, bm1, wm2, bm2, out);
}

// round 6
// speedup vs baseline: 1.0659x; 1.0582x over previous
#include <cuda_runtime.h>
#include <cstdint>
#include <cstring>

// ============================================================================
// Sparse masked CNN pyramid (14 levels) + MLP head — round 6.
//   build_all0 (also dups weights, blocks 0..116)
//   build_top
//   conv1
//   convk L1..L7   (software-pipelined tap prefetch; conflict-free STS)
//   tail           (levels 8..13 + MLP + re-zero state for next replay)
// g_cnt / g_pools are zero at load and re-zeroed by tail each run.
// ============================================================================

#define CAP 131072
#define NLEV 14
#define IDX_TOTAL 5592407

__device__ __align__(16) float g_FA[CAP * 32];
__device__ __align__(16) float g_FB[CAP * 32];
__device__ __align__(16) float g_Wdup[13 * 9 * 2048];   // [lvl][tap][ci][ch pairs]
__device__ int   g_idx[IDX_TOTAL];
__device__ int   g_pos[NLEV * CAP];
__device__ int   g_cnt[NLEV];              // zero-init; tail re-zeroes
__device__ float g_pools[NLEV * 32];       // zero-init; tail re-zeroes

__constant__ int c_LS[NLEV]   = {2048,1024,512,256,128,64,32,16,8,4,2,1,1,1};
__constant__ int c_IOFS[NLEV] = {0,4194304,5242880,5505024,5570560,5586944,5591040,
                                 5592064,5592320,5592384,5592400,5592404,5592405,5592406};

#define FMA2(d, a, b, c) \
    asm("fma.rn.f32x2 %0, %1, %2, %3;" : "=l"(d) : "l"(a), "l"(b), "l"(c))

__device__ __forceinline__ float2 upk(unsigned long long a) {
    float2 f; memcpy(&f, &a, 8); return f;
}

// ---- block compaction step (1024-thread blocks only) -------------------------
__device__ __forceinline__ void emit(int level, bool act, int lin, int posword,
                                     int iofs, unsigned* bitdst) {
    __shared__ int ewcnt[32];
    __shared__ int ewbase[32];
    __shared__ int ebbase;
    int tid = threadIdx.x, wid = tid >> 5, lane = tid & 31;
    unsigned m = __ballot_sync(0xffffffffu, act);
    if (lane == 0) {
        ewcnt[wid] = __popc(m);
        if (bitdst) bitdst[wid] = m;
    }
    __syncthreads();
    if (tid < 32) {
        int cc = ewcnt[tid];
        int x = cc;
        #pragma unroll
        for (int o = 1; o < 32; o <<= 1) {
            int y = __shfl_up_sync(0xffffffffu, x, o);
            if (tid >= o) x += y;
        }
        ewbase[tid] = x - cc;
        if (tid == 31) ebbase = atomicAdd(&g_cnt[level], x);
    }
    __syncthreads();
    int idx = -1;
    if (act) {
        idx = ebbase + ewbase[wid] + __popc(m & ((1u << lane) - 1u));
        if (idx < CAP) g_pos[level * CAP + idx] = posword;
        else idx = -1;
    }
    if (lin >= 0) g_idx[iofs + lin] = idx;
    __syncthreads();
}

__device__ __forceinline__ int getbit(const unsigned* a, int c) {
    return (a[c >> 5] >> (c & 31)) & 1;
}

// ---- levels 0..7, block = 128x128 base tile; blocks 0..116 also dup weights --
__global__ __launch_bounds__(1024) void build_all0(const float* __restrict__ mask,
                                                   const float* __restrict__ ws) {
    if (blockIdx.x < 117) {   // 13*9*32*32 = 119808 = 117 * 1024
        int t = blockIdx.x * 1024 + threadIdx.x;
        float w = ws[t];
        int ch = t & 31, rest = t >> 5;
        g_Wdup[rest * 64 + ch * 2]     = w;
        g_Wdup[rest * 64 + ch * 2 + 1] = w;
    }

    __shared__ unsigned a0[512];
    __shared__ unsigned a1[128];
    __shared__ unsigned a2[32];
    __shared__ unsigned a3[8];
    __shared__ unsigned a4[32];
    __shared__ unsigned a5[32];
    __shared__ unsigned a6[32];
    int tid = threadIdx.x;
    int tx = blockIdx.x & 15, ty = blockIdx.x >> 4;

    for (int r = 0; r < 16; r++) {
        int c = r * 1024 + tid;
        int li = c >> 7, lj = c & 127;
        int i = ty * 128 + li, j = tx * 128 + lj;
        bool act = (mask[i * 2048 + j] != 0.0f);
        emit(0, act, i * 2048 + j, (i << 16) | j, c_IOFS[0], a0 + r * 32);
    }
    unsigned* bits[8] = {a0, a1, a2, a3, a4, a5, a6, nullptr};
    #pragma unroll
    for (int L = 1; L <= 7; L++) {
        int t = 128 >> L;
        int cells = t * t;
        int chunks = (cells + 1023) >> 10;
        int tprev = t * 2;
        for (int r = 0; r < chunks; r++) {
            int c = r * 1024 + tid;
            bool act = false;
            int lin = -1, pw = 0;
            if (c < cells) {
                int li = c / t, lj = c - li * t;
                int c00 = (2 * li) * tprev + 2 * lj;
                const unsigned* pb = bits[L - 1];
                act = getbit(pb, c00) | getbit(pb, c00 + 1) |
                      getbit(pb, c00 + tprev) | getbit(pb, c00 + tprev + 1);
                int i = ty * t + li, j = tx * t + lj;
                lin = i * (2048 >> L) + j;
                pw = (i << 16) | j;
            }
            emit(L, act, lin, pw, c_IOFS[L], (L < 7) ? (bits[L] + r * 32) : nullptr);
        }
    }
}

// ---- levels 8..13, single block -----------------------------------------------
__global__ __launch_bounds__(1024) void build_top() {
    int tid = threadIdx.x;
    for (int k = 8; k < NLEV; k++) {
        int s = c_LS[k], sp = c_LS[k - 1];
        int cells = s * s;
        const int* Ip = g_idx + c_IOFS[k - 1];
        bool act = false;
        int lin = -1, pw = 0;
        if (tid < cells) {
            int i = tid / s, j = tid - i * s;
            #pragma unroll
            for (int di = 0; di < 2; di++)
                #pragma unroll
                for (int dj = 0; dj < 2; dj++) {
                    int r = 2 * i + di, cc = 2 * j + dj;
                    if (r < sp && cc < sp && Ip[r * sp + cc] >= 0) act = true;
                }
            lin = tid;
            pw = (i << 16) | j;
        }
        emit(k, act, lin, pw, c_IOFS[k], nullptr);
    }
}

// ---- level-0 conv: 5x5, cin=1 -> 32 ---------------------------------------------
__global__ void conv1_kernel(const float* __restrict__ x, const float* __restrict__ w1) {
    __shared__ float sw[800];
    __shared__ float bsum[32];
    int tid = threadIdx.x;
    for (int t = tid; t < 800; t += 256) sw[t] = w1[t];
    if (tid < 32) bsum[tid] = 0.f;
    __syncthreads();

    int n = min(g_cnt[0], CAP);
    int lane = tid & 31;
    int gw = (blockIdx.x * 256 + tid) >> 5;
    int nw = (gridDim.x * 256) >> 5;
    float pool = 0.f;
    for (int p = gw; p < n; p += nw) {
        int pw = g_pos[p];
        int i = pw >> 16, j = pw & 0xffff;
        float acc = 0.f;
        #pragma unroll
        for (int dy = 0; dy < 5; dy++) {
            int r = i + dy - 2;
            if ((unsigned)r < 2048u) {
                #pragma unroll
                for (int dx = 0; dx < 5; dx++) {
                    int cc = j + dx - 2;
                    if ((unsigned)cc < 2048u)
                        acc = fmaf(x[r * 2048 + cc], sw[(dy * 5 + dx) * 32 + lane], acc);
                }
            }
        }
        acc = fmaxf(acc, 0.f);
        g_FA[(size_t)p * 32 + lane] = acc;
        pool += acc;
    }
    atomicAdd(&bsum[lane], pool);
    __syncthreads();
    if (tid < 32) atomicAdd(&g_pools[tid], bsum[tid]);
}

// ---- levels 1..7: pipelined sparse tile-GEMM (128 pos x 32 ch), FFMA2 ----------
// SA_STRIDE = 132: multiple of 4 floats -> every LDS.128 16B-aligned.
// Gather channel mapping: thread parity cb in {0,4}; blocks ci = cb + 8q.
// Bank check (stride mod 32 = 4): pair lanes differ by ci=4 -> +16 banks; rows
// walk +1 bank -> each warp's STS hits all 32 banks exactly once. Conflict-free.
#define SA_STRIDE 132
#define CONVK_SMEM (18432 * 4 + 32 * SA_STRIDE * 4 + 9 * 128 * 4 + 32 * 4)

__device__ __forceinline__ void prefetch_tap(const float* __restrict__ Fprev,
                                             const int* __restrict__ sNbr,
                                             int d, int row, int cb, float4 r[4]) {
    int nb = sNbr[d * 128 + row];
    if (nb >= 0) {
        const float* src = Fprev + (size_t)nb * 32 + cb;
        r[0] = *(const float4*)(src);
        r[1] = *(const float4*)(src + 8);
        r[2] = *(const float4*)(src + 16);
        r[3] = *(const float4*)(src + 24);
    } else {
        r[0] = r[1] = r[2] = r[3] = make_float4(0.f, 0.f, 0.f, 0.f);
    }
}

__global__ __launch_bounds__(256) void convk_kernel(int level, int sprev,
                                                    int iofs_prev) {
    extern __shared__ float smem[];
    float* sW   = smem;                                  // [9][32][64] dup pairs
    float* sA   = smem + 18432;                          // [32][SA_STRIDE]
    int*   sNbr = (int*)(smem + 18432 + 32 * SA_STRIDE); // [9][128]
    float* spool = (float*)(sNbr + 9 * 128);             // [32]

    const float* Fprev;
    float* Fcur;
    if (level & 1) { Fprev = g_FA; Fcur = g_FB; }
    else           { Fprev = g_FB; Fcur = g_FA; }

    int tid = threadIdx.x;
    // stage duplicated weights ONCE per block (72KB)
    {
        const float4* src = (const float4*)(g_Wdup + (size_t)(level - 1) * 18432);
        float4* dst = (float4*)sW;
        #pragma unroll
        for (int t = 0; t < 18; t++) dst[tid + t * 256] = src[tid + t * 256];
    }
    if (tid < 32) spool[tid] = 0.f;
    __syncthreads();

    int n = min(g_cnt[level], CAP);
    const int* posl = g_pos + level * CAP;
    const int* Iprev = g_idx + iofs_prev;

    int ch  = (tid & 7) * 4;      // 4 output channels
    int pg  = tid >> 3;           // position group (4 positions)
    int row = tid >> 1;           // gather row
    int cb  = (tid & 1) * 4;      // gather channel base (interleaved 4-blocks)
    int rr  = tid & 127;          // sNbr row for this thread
    float pl0 = 0.f, pl1 = 0.f, pl2 = 0.f, pl3 = 0.f;

    for (int base = blockIdx.x * 128; base < n; base += gridDim.x * 128) {
        // ---- neighbor indices (all 256 threads; taps split 5/4) ----
        {
            int p = base + rr;
            bool ok = (p < n);
            int pi = 0, pj = 0;
            if (ok) {
                int pw = posl[p];
                pi = pw >> 16; pj = pw & 0xffff;
            }
            int d0 = (tid < 128) ? 0 : 5;
            int d1 = (tid < 128) ? 5 : 9;
            for (int d = d0; d < d1; d++) {
                int nb = -1;
                if (ok) {
                    int r = 2 * pi + d / 3 - 1;
                    int cc = 2 * pj + d % 3 - 1;
                    if ((unsigned)r < (unsigned)sprev && (unsigned)cc < (unsigned)sprev)
                        nb = Iprev[r * sprev + cc];
                }
                sNbr[d * 128 + rr] = nb;
            }
        }
        __syncthreads();

        unsigned long long acc[8] = {0ull,0ull,0ull,0ull,0ull,0ull,0ull,0ull};
        float4 r[4];
        prefetch_tap(Fprev, sNbr, 0, row, cb, r);

        #pragma unroll 1
        for (int d = 0; d < 9; d++) {
            // store prefetched tap d into sA[ci][row], ci = cb + 8q + 0..3
            #pragma unroll
            for (int q = 0; q < 4; q++) {
                int ci = cb + 8 * q;
                sA[(ci + 0) * SA_STRIDE + row] = r[q].x;
                sA[(ci + 1) * SA_STRIDE + row] = r[q].y;
                sA[(ci + 2) * SA_STRIDE + row] = r[q].z;
                sA[(ci + 3) * SA_STRIDE + row] = r[q].w;
            }
            __syncthreads();
            if (d < 8) prefetch_tap(Fprev, sNbr, d + 1, row, cb, r);  // hide LDG
            const float* wd = sW + d * 2048;
            #pragma unroll
            for (int ci = 0; ci < 32; ci++) {
                ulonglong2 v  = *(const ulonglong2*)(sA + ci * SA_STRIDE + pg * 4);
                ulonglong2 wa = *(const ulonglong2*)(wd + ci * 64 + ch * 2);
                ulonglong2 wb = *(const ulonglong2*)(wd + ci * 64 + ch * 2 + 4);
                FMA2(acc[0], v.x, wa.x, acc[0]);
                FMA2(acc[1], v.x, wa.y, acc[1]);
                FMA2(acc[2], v.x, wb.x, acc[2]);
                FMA2(acc[3], v.x, wb.y, acc[3]);
                FMA2(acc[4], v.y, wa.x, acc[4]);
                FMA2(acc[5], v.y, wa.y, acc[5]);
                FMA2(acc[6], v.y, wb.x, acc[6]);
                FMA2(acc[7], v.y, wb.y, acc[7]);
            }
            __syncthreads();
        }

        // epilogue: relu, store, pool
        float2 a0 = upk(acc[0]), a1 = upk(acc[1]), a2 = upk(acc[2]), a3 = upk(acc[3]);
        float2 b0 = upk(acc[4]), b1 = upk(acc[5]), b2 = upk(acc[6]), b3 = upk(acc[7]);
        float4 vq[4];
        vq[0] = make_float4(a0.x, a1.x, a2.x, a3.x);
        vq[1] = make_float4(a0.y, a1.y, a2.y, a3.y);
        vq[2] = make_float4(b0.x, b1.x, b2.x, b3.x);
        vq[3] = make_float4(b0.y, b1.y, b2.y, b3.y);
        #pragma unroll
        for (int q = 0; q < 4; q++) {
            int p = base + pg * 4 + q;
            if (p < n) {
                float4 v;
                v.x = fmaxf(vq[q].x, 0.f);
                v.y = fmaxf(vq[q].y, 0.f);
                v.z = fmaxf(vq[q].z, 0.f);
                v.w = fmaxf(vq[q].w, 0.f);
                *(float4*)(Fcur + (size_t)p * 32 + ch) = v;
                pl0 += v.x; pl1 += v.y; pl2 += v.z; pl3 += v.w;
            }
        }
    }
    pl0 += __shfl_xor_sync(0xffffffffu, pl0, 8); pl0 += __shfl_xor_sync(0xffffffffu, pl0, 16);
    pl1 += __shfl_xor_sync(0xffffffffu, pl1, 8); pl1 += __shfl_xor_sync(0xffffffffu, pl1, 16);
    pl2 += __shfl_xor_sync(0xffffffffu, pl2, 8); pl2 += __shfl_xor_sync(0xffffffffu, pl2, 16);
    pl3 += __shfl_xor_sync(0xffffffffu, pl3, 8); pl3 += __shfl_xor_sync(0xffffffffu, pl3, 16);
    __syncthreads();
    if ((tid & 31) < 8) {
        atomicAdd(&spool[ch + 0], pl0);
        atomicAdd(&spool[ch + 1], pl1);
        atomicAdd(&spool[ch + 2], pl2);
        atomicAdd(&spool[ch + 3], pl3);
    }
    __syncthreads();
    if (tid < 32) atomicAdd(&g_pools[level * 32 + tid], spool[tid]);
}

// ---- tail: levels 8..13 + MLP + re-zero state (1 block) --------------------------
__global__ __launch_bounds__(256) void tail_kernel(
    const float* __restrict__ ws,
    const float* __restrict__ wm1, const float* __restrict__ bm1,
    const float* __restrict__ wm2, const float* __restrict__ bm2,
    float* __restrict__ out) {
    __shared__ float spool[32];
    int tid = threadIdx.x, wid = tid >> 5, lane = tid & 31;

    for (int k = 8; k < NLEV; k++) {
        int n = min(g_cnt[k], CAP);
        int sp = c_LS[k - 1];
        const int* Ip = g_idx + c_IOFS[k - 1];
        const float* Fp = (k & 1) ? g_FA : g_FB;
        float* Fc = (k & 1) ? g_FB : g_FA;
        const float* W = ws + (size_t)(k - 1) * 9216;
        if (tid < 32) spool[tid] = 0.f;
        __syncthreads();
        float pool = 0.f;
        for (int p = wid; p < n; p += 8) {
            int pw = g_pos[k * CAP + p];
            int pi = pw >> 16, pj = pw & 0xffff;
            float acc = 0.f;
            for (int d = 0; d < 9; d++) {
                int r = 2 * pi + d / 3 - 1;
                int cc = 2 * pj + d % 3 - 1;
                if ((unsigned)r < (unsigned)sp && (unsigned)cc < (unsigned)sp) {
                    int nb = Ip[r * sp + cc];
                    if (nb >= 0) {
                        float row = Fp[(size_t)nb * 32 + lane];
                        const float* wd = W + d * 1024;
                        #pragma unroll
                        for (int ci = 0; ci < 32; ci++)
                            acc = fmaf(__shfl_sync(0xffffffffu, row, ci),
                                       wd[ci * 32 + lane], acc);
                    }
                }
            }
            acc = fmaxf(acc, 0.f);
            Fc[(size_t)p * 32 + lane] = acc;
            pool += acc;
        }
        atomicAdd(&spool[lane], pool);
        __syncthreads();
        if (tid < 32) g_pools[k * 32 + tid] = spool[tid];
        __syncthreads();
    }

    __shared__ float sf[448];
    __shared__ float sh[256];
    for (int i = tid; i < 448; i += 256) {
        int k = i >> 5;
        float cnt = (float)max(g_cnt[k], 1);
        sf[i] = g_pools[i] / cnt;
    }
    __syncthreads();
    {
        float acc = bm1[tid];
        #pragma unroll 4
        for (int i = 0; i < 448; i++) acc = fmaf(sf[i], wm1[i * 256 + tid], acc);
        sh[tid] = fmaxf(acc, 0.f);
    }
    __syncthreads();
    if (tid < 128) {
        float acc = bm2[tid];
        #pragma unroll 4
        for (int j = 0; j < 256; j++) acc = fmaf(sh[j], wm2[j * 128 + tid], acc);
        out[tid] = acc;
    }

    // re-zero state so the next graph replay starts clean
    __syncthreads();
    for (int i = tid; i < NLEV * 32; i += 256) g_pools[i] = 0.f;
    if (tid < NLEV) g_cnt[tid] = 0;
}

// ---- host launch --------------------------------------------------------------------
static const int H_LS[NLEV]   = {2048,1024,512,256,128,64,32,16,8,4,2,1,1,1};
static const int H_IOFS[NLEV] = {0,4194304,5242880,5505024,5570560,5586944,5591040,
                                 5592064,5592320,5592384,5592400,5592404,5592405,5592406};

extern "C" void kernel_launch(void* const* d_in, const int* in_sizes, int n_in,
                              void* d_out, int out_size) {
    const float* x    = (const float*)d_in[0];
    const float* mask = (const float*)d_in[1];
    const float* w1   = (const float*)d_in[2];
    const float* ws   = (const float*)d_in[3];
    const float* wm1  = (const float*)d_in[4];
    const float* bm1  = (const float*)d_in[5];
    const float* wm2  = (const float*)d_in[6];
    const float* bm2  = (const float*)d_in[7];
    float* out = (float*)d_out;

    cudaFuncSetAttribute((const void*)convk_kernel,
                         cudaFuncAttributeMaxDynamicSharedMemorySize, CONVK_SMEM);

    build_all0<<<256, 1024>>>(mask, ws);
    build_top<<<1, 1024>>>();
    conv1_kernel<<<2048, 256>>>(x, w1);

    static const int cgrid[8] = {0, 324, 308, 246, 120, 32, 8, 2};
    for (int k = 1; k <= 7; k++)
        convk_kernel<<<cgrid[k], 256, CONVK_SMEM>>>(k, H_LS[k - 1], H_IOFS[k - 1]);

    tail_kernel<<<1, 256>>>(ws, wm1, bm1, wm2, bm2, out);
}

// round 7
// speedup vs baseline: 1.3659x; 1.2815x over previous
#include <cuda_runtime.h>
#include <cstdint>
#include <cstring>

// ============================================================================
// Sparse masked CNN pyramid (14 levels) + MLP head — round 7.
// convk redesign: thread = 2 positions x 32 channels, activations LDG->reg,
// weights smem-broadcast, no barriers in main loop, warp-uniform tap skip.
// ============================================================================

#define CAP 131072
#define NLEV 14
#define IDX_TOTAL 5592407

__device__ __align__(16) float g_FA[CAP * 32];
__device__ __align__(16) float g_FB[CAP * 32];
__device__ int   g_idx[IDX_TOTAL];
__device__ int   g_pos[NLEV * CAP];
__device__ int   g_cnt[NLEV];              // zero-init; tail re-zeroes
__device__ float g_pools[NLEV * 32];       // zero-init; tail re-zeroes

__constant__ int c_LS[NLEV]   = {2048,1024,512,256,128,64,32,16,8,4,2,1,1,1};
__constant__ int c_IOFS[NLEV] = {0,4194304,5242880,5505024,5570560,5586944,5591040,
                                 5592064,5592320,5592384,5592400,5592404,5592405,5592406};

#define FMA2(d, a, b, c) \
    asm("fma.rn.f32x2 %0, %1, %2, %3;" : "=l"(d) : "l"(a), "l"(b), "l"(c))
#define ADD2(d, a, b) \
    asm("add.rn.f32x2 %0, %1, %2;" : "=l"(d) : "l"(a), "l"(b))
#define PACK_DUP(d, a) \
    do { unsigned _u = __float_as_uint(a); \
         asm("mov.b64 %0, {%1, %1};" : "=l"(d) : "r"(_u)); } while (0)

__device__ __forceinline__ float2 upk(unsigned long long a) {
    float2 f; memcpy(&f, &a, 8); return f;
}

// ---- block compaction step (1024-thread blocks only) -------------------------
__device__ __forceinline__ void emit(int level, bool act, int lin, int posword,
                                     int iofs, unsigned* bitdst) {
    __shared__ int ewcnt[32];
    __shared__ int ewbase[32];
    __shared__ int ebbase;
    int tid = threadIdx.x, wid = tid >> 5, lane = tid & 31;
    unsigned m = __ballot_sync(0xffffffffu, act);
    if (lane == 0) {
        ewcnt[wid] = __popc(m);
        if (bitdst) bitdst[wid] = m;
    }
    __syncthreads();
    if (tid < 32) {
        int cc = ewcnt[tid];
        int x = cc;
        #pragma unroll
        for (int o = 1; o < 32; o <<= 1) {
            int y = __shfl_up_sync(0xffffffffu, x, o);
            if (tid >= o) x += y;
        }
        ewbase[tid] = x - cc;
        if (tid == 31) ebbase = atomicAdd(&g_cnt[level], x);
    }
    __syncthreads();
    int idx = -1;
    if (act) {
        idx = ebbase + ewbase[wid] + __popc(m & ((1u << lane) - 1u));
        if (idx < CAP) g_pos[level * CAP + idx] = posword;
        else idx = -1;
    }
    if (lin >= 0) g_idx[iofs + lin] = idx;
    __syncthreads();
}

__device__ __forceinline__ int getbit(const unsigned* a, int c) {
    return (a[c >> 5] >> (c & 31)) & 1;
}

// ---- levels 0..7, block = 128x128 base tile -----------------------------------
__global__ __launch_bounds__(1024) void build_all0(const float* __restrict__ mask) {
    __shared__ unsigned a0[512];
    __shared__ unsigned a1[128];
    __shared__ unsigned a2[32];
    __shared__ unsigned a3[8];
    __shared__ unsigned a4[32];
    __shared__ unsigned a5[32];
    __shared__ unsigned a6[32];
    int tid = threadIdx.x;
    int tx = blockIdx.x & 15, ty = blockIdx.x >> 4;

    for (int r = 0; r < 16; r++) {
        int c = r * 1024 + tid;
        int li = c >> 7, lj = c & 127;
        int i = ty * 128 + li, j = tx * 128 + lj;
        bool act = (mask[i * 2048 + j] != 0.0f);
        emit(0, act, i * 2048 + j, (i << 16) | j, c_IOFS[0], a0 + r * 32);
    }
    unsigned* bits[8] = {a0, a1, a2, a3, a4, a5, a6, nullptr};
    #pragma unroll
    for (int L = 1; L <= 7; L++) {
        int t = 128 >> L;
        int cells = t * t;
        int chunks = (cells + 1023) >> 10;
        int tprev = t * 2;
        for (int r = 0; r < chunks; r++) {
            int c = r * 1024 + tid;
            bool act = false;
            int lin = -1, pw = 0;
            if (c < cells) {
                int li = c / t, lj = c - li * t;
                int c00 = (2 * li) * tprev + 2 * lj;
                const unsigned* pb = bits[L - 1];
                act = getbit(pb, c00) | getbit(pb, c00 + 1) |
                      getbit(pb, c00 + tprev) | getbit(pb, c00 + tprev + 1);
                int i = ty * t + li, j = tx * t + lj;
                lin = i * (2048 >> L) + j;
                pw = (i << 16) | j;
            }
            emit(L, act, lin, pw, c_IOFS[L], (L < 7) ? (bits[L] + r * 32) : nullptr);
        }
    }
}

// ---- levels 8..13, single block -----------------------------------------------
__global__ __launch_bounds__(1024) void build_top() {
    int tid = threadIdx.x;
    for (int k = 8; k < NLEV; k++) {
        int s = c_LS[k], sp = c_LS[k - 1];
        int cells = s * s;
        const int* Ip = g_idx + c_IOFS[k - 1];
        bool act = false;
        int lin = -1, pw = 0;
        if (tid < cells) {
            int i = tid / s, j = tid - i * s;
            #pragma unroll
            for (int di = 0; di < 2; di++)
                #pragma unroll
                for (int dj = 0; dj < 2; dj++) {
                    int r = 2 * i + di, cc = 2 * j + dj;
                    if (r < sp && cc < sp && Ip[r * sp + cc] >= 0) act = true;
                }
            lin = tid;
            pw = (i << 16) | j;
        }
        emit(k, act, lin, pw, c_IOFS[k], nullptr);
    }
}

// ---- level-0 conv: 5x5, cin=1 -> 32 ---------------------------------------------
__global__ void conv1_kernel(const float* __restrict__ x, const float* __restrict__ w1) {
    __shared__ float sw[800];
    __shared__ float bsum[32];
    int tid = threadIdx.x;
    for (int t = tid; t < 800; t += 256) sw[t] = w1[t];
    if (tid < 32) bsum[tid] = 0.f;
    __syncthreads();

    int n = min(g_cnt[0], CAP);
    int lane = tid & 31;
    int gw = (blockIdx.x * 256 + tid) >> 5;
    int nw = (gridDim.x * 256) >> 5;
    float pool = 0.f;
    for (int p = gw; p < n; p += nw) {
        int pw = g_pos[p];
        int i = pw >> 16, j = pw & 0xffff;
        float acc = 0.f;
        #pragma unroll
        for (int dy = 0; dy < 5; dy++) {
            int r = i + dy - 2;
            if ((unsigned)r < 2048u) {
                #pragma unroll
                for (int dx = 0; dx < 5; dx++) {
                    int cc = j + dx - 2;
                    if ((unsigned)cc < 2048u)
                        acc = fmaf(x[r * 2048 + cc], sw[(dy * 5 + dx) * 32 + lane], acc);
                }
            }
        }
        acc = fmaxf(acc, 0.f);
        g_FA[(size_t)p * 32 + lane] = acc;
        pool += acc;
    }
    atomicAdd(&bsum[lane], pool);
    __syncthreads();
    if (tid < 32) atomicAdd(&g_pools[tid], bsum[tid]);
}

// ---- levels 1..7: reg-resident sparse conv ---------------------------------------
// 128 threads/block, thread = 2 positions x 32 ch; tile = 256 positions.
// Weights in smem (natural layout, warp-uniform broadcast reads).
// No __syncthreads in the tile loop; warp-uniform tap skip via ballot.
__global__ __launch_bounds__(128) void convk_kernel(const float* __restrict__ ws,
                                                    int level, int sprev, int iofs_prev) {
    __shared__ float sW[9216];       // [tap][ci][co]
    __shared__ float spool[32];
    const float* __restrict__ Fprev = (level & 1) ? g_FA : g_FB;
    float* __restrict__ Fcur = (level & 1) ? g_FB : g_FA;
    int tid = threadIdx.x;
    {
        const float4* src = (const float4*)(ws + (size_t)(level - 1) * 9216);
        float4* dst = (float4*)sW;
        #pragma unroll
        for (int t = 0; t < 18; t++) dst[tid + t * 128] = src[tid + t * 128];
    }
    if (tid < 32) spool[tid] = 0.f;
    __syncthreads();

    int n = min(g_cnt[level], CAP);
    const int* __restrict__ posl = g_pos + level * CAP;
    const int* __restrict__ Iprev = g_idx + iofs_prev;

    unsigned long long pool[16];
    #pragma unroll
    for (int i = 0; i < 16; i++) pool[i] = 0ull;

    for (int base = blockIdx.x * 256; base < n; base += gridDim.x * 256) {
        int p0 = base + tid * 2, p1 = p0 + 1;
        // all 9 neighbor indices up-front (MLP: 18 independent LDGs in flight)
        int nb0[9], nb1[9];
        {
            int pw0 = (p0 < n) ? posl[p0] : -1;
            int pw1 = (p1 < n) ? posl[p1] : -1;
            #pragma unroll
            for (int d = 0; d < 9; d++) {
                int dr = d / 3 - 1, dc = d % 3 - 1;
                int a = -1, b = -1;
                if (pw0 >= 0) {
                    int r = 2 * (pw0 >> 16) + dr, c = 2 * (pw0 & 0xffff) + dc;
                    if ((unsigned)r < (unsigned)sprev && (unsigned)c < (unsigned)sprev)
                        a = Iprev[r * sprev + c];
                }
                if (pw1 >= 0) {
                    int r = 2 * (pw1 >> 16) + dr, c = 2 * (pw1 & 0xffff) + dc;
                    if ((unsigned)r < (unsigned)sprev && (unsigned)c < (unsigned)sprev)
                        b = Iprev[r * sprev + c];
                }
                nb0[d] = a; nb1[d] = b;
            }
        }
        unsigned long long acc0[16], acc1[16];
        #pragma unroll
        for (int i = 0; i < 16; i++) { acc0[i] = 0ull; acc1[i] = 0ull; }

        #pragma unroll 1
        for (int d = 0; d < 9; d++) {
            bool v0 = nb0[d] >= 0, v1 = nb1[d] >= 0;
            if (!__ballot_sync(0xffffffffu, v0 || v1)) continue;   // warp-uniform skip
            const float* a0p = Fprev + (size_t)max(nb0[d], 0) * 32;
            const float* a1p = Fprev + (size_t)max(nb1[d], 0) * 32;
            const float* wd = sW + d * 1024;
            #pragma unroll
            for (int q = 0; q < 8; q++) {
                float4 x0 = v0 ? *(const float4*)(a0p + q * 4) : make_float4(0.f,0.f,0.f,0.f);
                float4 x1 = v1 ? *(const float4*)(a1p + q * 4) : make_float4(0.f,0.f,0.f,0.f);
                #pragma unroll
                for (int j = 0; j < 4; j++) {
                    int ci = q * 4 + j;
                    float e0 = (j == 0) ? x0.x : (j == 1) ? x0.y : (j == 2) ? x0.z : x0.w;
                    float e1 = (j == 0) ? x1.x : (j == 1) ? x1.y : (j == 2) ? x1.z : x1.w;
                    unsigned long long A0, A1;
                    PACK_DUP(A0, e0);
                    PACK_DUP(A1, e1);
                    const ulonglong2* w2 = (const ulonglong2*)(wd + ci * 32);
                    #pragma unroll
                    for (int h = 0; h < 8; h++) {
                        ulonglong2 w = w2[h];                   // broadcast LDS.128
                        FMA2(acc0[2*h],   A0, w.x, acc0[2*h]);
                        FMA2(acc0[2*h+1], A0, w.y, acc0[2*h+1]);
                        FMA2(acc1[2*h],   A1, w.x, acc1[2*h]);
                        FMA2(acc1[2*h+1], A1, w.y, acc1[2*h+1]);
                    }
                }
            }
        }

        // epilogue: relu (packed), pool, store
        #pragma unroll
        for (int i = 0; i < 16; i++) {
            float2 f0 = upk(acc0[i]);
            f0.x = fmaxf(f0.x, 0.f); f0.y = fmaxf(f0.y, 0.f);
            unsigned long long P0;
            asm("mov.b64 %0, {%1, %2};" : "=l"(P0)
                : "r"(__float_as_uint(f0.x)), "r"(__float_as_uint(f0.y)));
            ADD2(pool[i], P0, pool[i]);
            acc0[i] = P0;
            float2 f1 = upk(acc1[i]);
            f1.x = fmaxf(f1.x, 0.f); f1.y = fmaxf(f1.y, 0.f);
            unsigned long long P1;
            asm("mov.b64 %0, {%1, %2};" : "=l"(P1)
                : "r"(__float_as_uint(f1.x)), "r"(__float_as_uint(f1.y)));
            ADD2(pool[i], P1, pool[i]);
            acc1[i] = P1;
        }
        if (p0 < n) {
            ulonglong2* dst = (ulonglong2*)(Fcur + (size_t)p0 * 32);
            #pragma unroll
            for (int h = 0; h < 8; h++)
                dst[h] = make_ulonglong2(acc0[2*h], acc0[2*h+1]);
        }
        if (p1 < n) {
            ulonglong2* dst = (ulonglong2*)(Fcur + (size_t)p1 * 32);
            #pragma unroll
            for (int h = 0; h < 8; h++)
                dst[h] = make_ulonglong2(acc1[2*h], acc1[2*h+1]);
        }
    }

    // pool: butterfly reduce across warp (packed), then smem, then global
    #pragma unroll
    for (int i = 0; i < 16; i++) {
        #pragma unroll
        for (int off = 16; off; off >>= 1) {
            unsigned long long o = __shfl_xor_sync(0xffffffffu, pool[i], off);
            ADD2(pool[i], o, pool[i]);
        }
    }
    if ((tid & 31) == 0) {
        #pragma unroll
        for (int i = 0; i < 16; i++) {
            float2 f = upk(pool[i]);
            atomicAdd(&spool[2*i],     f.x);
            atomicAdd(&spool[2*i + 1], f.y);
        }
    }
    __syncthreads();
    if (tid < 32) atomicAdd(&g_pools[level * 32 + tid], spool[tid]);
}

// ---- tail: levels 8..13 + MLP + re-zero state (1 block) --------------------------
__global__ __launch_bounds__(256) void tail_kernel(
    const float* __restrict__ ws,
    const float* __restrict__ wm1, const float* __restrict__ bm1,
    const float* __restrict__ wm2, const float* __restrict__ bm2,
    float* __restrict__ out) {
    __shared__ float spool[32];
    int tid = threadIdx.x, wid = tid >> 5, lane = tid & 31;

    for (int k = 8; k < NLEV; k++) {
        int n = min(g_cnt[k], CAP);
        int sp = c_LS[k - 1];
        const int* Ip = g_idx + c_IOFS[k - 1];
        const float* Fp = (k & 1) ? g_FA : g_FB;
        float* Fc = (k & 1) ? g_FB : g_FA;
        const float* W = ws + (size_t)(k - 1) * 9216;
        if (tid < 32) spool[tid] = 0.f;
        __syncthreads();
        float pool = 0.f;
        for (int p = wid; p < n; p += 8) {
            int pw = g_pos[k * CAP + p];
            int pi = pw >> 16, pj = pw & 0xffff;
            float acc = 0.f;
            for (int d = 0; d < 9; d++) {
                int r = 2 * pi + d / 3 - 1;
                int cc = 2 * pj + d % 3 - 1;
                if ((unsigned)r < (unsigned)sp && (unsigned)cc < (unsigned)sp) {
                    int nb = Ip[r * sp + cc];
                    if (nb >= 0) {
                        float row = Fp[(size_t)nb * 32 + lane];
                        const float* wd = W + d * 1024;
                        #pragma unroll
                        for (int ci = 0; ci < 32; ci++)
                            acc = fmaf(__shfl_sync(0xffffffffu, row, ci),
                                       wd[ci * 32 + lane], acc);
                    }
                }
            }
            acc = fmaxf(acc, 0.f);
            Fc[(size_t)p * 32 + lane] = acc;
            pool += acc;
        }
        atomicAdd(&spool[lane], pool);
        __syncthreads();
        if (tid < 32) g_pools[k * 32 + tid] = spool[tid];
        __syncthreads();
    }

    __shared__ float sf[448];
    __shared__ float sh[256];
    for (int i = tid; i < 448; i += 256) {
        int k = i >> 5;
        float cnt = (float)max(g_cnt[k], 1);
        sf[i] = g_pools[i] / cnt;
    }
    __syncthreads();
    {
        float acc = bm1[tid];
        #pragma unroll 4
        for (int i = 0; i < 448; i++) acc = fmaf(sf[i], wm1[i * 256 + tid], acc);
        sh[tid] = fmaxf(acc, 0.f);
    }
    __syncthreads();
    if (tid < 128) {
        float acc = bm2[tid];
        #pragma unroll 4
        for (int j = 0; j < 256; j++) acc = fmaf(sh[j], wm2[j * 128 + tid], acc);
        out[tid] = acc;
    }

    // re-zero state so the next graph replay starts clean
    __syncthreads();
    for (int i = tid; i < NLEV * 32; i += 256) g_pools[i] = 0.f;
    if (tid < NLEV) g_cnt[tid] = 0;
}

// ---- host launch --------------------------------------------------------------------
static const int H_LS[NLEV]   = {2048,1024,512,256,128,64,32,16,8,4,2,1,1,1};
static const int H_IOFS[NLEV] = {0,4194304,5242880,5505024,5570560,5586944,5591040,
                                 5592064,5592320,5592384,5592400,5592404,5592405,5592406};

extern "C" void kernel_launch(void* const* d_in, const int* in_sizes, int n_in,
                              void* d_out, int out_size) {
    const float* x    = (const float*)d_in[0];
    const float* mask = (const float*)d_in[1];
    const float* w1   = (const float*)d_in[2];
    const float* ws   = (const float*)d_in[3];
    const float* wm1  = (const float*)d_in[4];
    const float* bm1  = (const float*)d_in[5];
    const float* wm2  = (const float*)d_in[6];
    const float* bm2  = (const float*)d_in[7];
    float* out = (float*)d_out;

    build_all0<<<256, 1024>>>(mask);
    build_top<<<1, 1024>>>();
    conv1_kernel<<<2048, 256>>>(x, w1);

    // 256-position tiles; stride loop handles any overflow beyond these grids
    static const int cgrid[8] = {0, 180, 172, 140, 64, 16, 4, 1};
    for (int k = 1; k <= 7; k++)
        convk_kernel<<<cgrid[k], 128>>>(ws, k, H_LS[k - 1], H_IOFS[k - 1]);

    tail_kernel<<<1, 256>>>(ws, wm1, bm1, wm2, bm2, out);
}

// round 8
// speedup vs baseline: 1.4998x; 1.0980x over previous
#include <cuda_runtime.h>
#include <cstdint>
#include <cstring>

// ============================================================================
// Sparse masked CNN pyramid (14 levels) + MLP head — round 8.
// convk: thread = 1 position x 16 channels (256 thr/block, 128-pos tile),
// activations LDG->reg, weights smem-broadcast, no barriers in main loop.
// ============================================================================

#define CAP 131072
#define NLEV 14
#define IDX_TOTAL 5592407

__device__ __align__(16) float g_FA[CAP * 32];
__device__ __align__(16) float g_FB[CAP * 32];
__device__ int   g_idx[IDX_TOTAL];
__device__ int   g_pos[NLEV * CAP];
__device__ int   g_cnt[NLEV];              // zero-init; tail re-zeroes
__device__ float g_pools[NLEV * 32];       // zero-init; tail re-zeroes

__constant__ int c_LS[NLEV]   = {2048,1024,512,256,128,64,32,16,8,4,2,1,1,1};
__constant__ int c_IOFS[NLEV] = {0,4194304,5242880,5505024,5570560,5586944,5591040,
                                 5592064,5592320,5592384,5592400,5592404,5592405,5592406};

#define FMA2(d, a, b, c) \
    asm("fma.rn.f32x2 %0, %1, %2, %3;" : "=l"(d) : "l"(a), "l"(b), "l"(c))
#define ADD2(d, a, b) \
    asm("add.rn.f32x2 %0, %1, %2;" : "=l"(d) : "l"(a), "l"(b))
#define PACK_DUP(d, a) \
    do { unsigned _u = __float_as_uint(a); \
         asm("mov.b64 %0, {%1, %1};" : "=l"(d) : "r"(_u)); } while (0)

__device__ __forceinline__ float2 upk(unsigned long long a) {
    float2 f; memcpy(&f, &a, 8); return f;
}

// ---- block compaction step (1024-thread blocks only) -------------------------
__device__ __forceinline__ void emit(int level, bool act, int lin, int posword,
                                     int iofs, unsigned* bitdst) {
    __shared__ int ewcnt[32];
    __shared__ int ewbase[32];
    __shared__ int ebbase;
    int tid = threadIdx.x, wid = tid >> 5, lane = tid & 31;
    unsigned m = __ballot_sync(0xffffffffu, act);
    if (lane == 0) {
        ewcnt[wid] = __popc(m);
        if (bitdst) bitdst[wid] = m;
    }
    __syncthreads();
    if (tid < 32) {
        int cc = ewcnt[tid];
        int x = cc;
        #pragma unroll
        for (int o = 1; o < 32; o <<= 1) {
            int y = __shfl_up_sync(0xffffffffu, x, o);
            if (tid >= o) x += y;
        }
        ewbase[tid] = x - cc;
        if (tid == 31) ebbase = atomicAdd(&g_cnt[level], x);
    }
    __syncthreads();
    int idx = -1;
    if (act) {
        idx = ebbase + ewbase[wid] + __popc(m & ((1u << lane) - 1u));
        if (idx < CAP) g_pos[level * CAP + idx] = posword;
        else idx = -1;
    }
    if (lin >= 0) g_idx[iofs + lin] = idx;
    __syncthreads();
}

__device__ __forceinline__ int getbit(const unsigned* a, int c) {
    return (a[c >> 5] >> (c & 31)) & 1;
}

// ---- levels 0..7, block = 128x128 base tile -----------------------------------
__global__ __launch_bounds__(1024) void build_all0(const float* __restrict__ mask) {
    __shared__ unsigned a0[512];
    __shared__ unsigned a1[128];
    __shared__ unsigned a2[32];
    __shared__ unsigned a3[8];
    __shared__ unsigned a4[32];
    __shared__ unsigned a5[32];
    __shared__ unsigned a6[32];
    int tid = threadIdx.x;
    int tx = blockIdx.x & 15, ty = blockIdx.x >> 4;

    for (int r = 0; r < 16; r++) {
        int c = r * 1024 + tid;
        int li = c >> 7, lj = c & 127;
        int i = ty * 128 + li, j = tx * 128 + lj;
        bool act = (mask[i * 2048 + j] != 0.0f);
        emit(0, act, i * 2048 + j, (i << 16) | j, c_IOFS[0], a0 + r * 32);
    }
    unsigned* bits[8] = {a0, a1, a2, a3, a4, a5, a6, nullptr};
    #pragma unroll
    for (int L = 1; L <= 7; L++) {
        int t = 128 >> L;
        int cells = t * t;
        int chunks = (cells + 1023) >> 10;
        int tprev = t * 2;
        for (int r = 0; r < chunks; r++) {
            int c = r * 1024 + tid;
            bool act = false;
            int lin = -1, pw = 0;
            if (c < cells) {
                int li = c / t, lj = c - li * t;
                int c00 = (2 * li) * tprev + 2 * lj;
                const unsigned* pb = bits[L - 1];
                act = getbit(pb, c00) | getbit(pb, c00 + 1) |
                      getbit(pb, c00 + tprev) | getbit(pb, c00 + tprev + 1);
                int i = ty * t + li, j = tx * t + lj;
                lin = i * (2048 >> L) + j;
                pw = (i << 16) | j;
            }
            emit(L, act, lin, pw, c_IOFS[L], (L < 7) ? (bits[L] + r * 32) : nullptr);
        }
    }
}

// ---- levels 8..13, single block -----------------------------------------------
__global__ __launch_bounds__(1024) void build_top() {
    int tid = threadIdx.x;
    for (int k = 8; k < NLEV; k++) {
        int s = c_LS[k], sp = c_LS[k - 1];
        int cells = s * s;
        const int* Ip = g_idx + c_IOFS[k - 1];
        bool act = false;
        int lin = -1, pw = 0;
        if (tid < cells) {
            int i = tid / s, j = tid - i * s;
            #pragma unroll
            for (int di = 0; di < 2; di++)
                #pragma unroll
                for (int dj = 0; dj < 2; dj++) {
                    int r = 2 * i + di, cc = 2 * j + dj;
                    if (r < sp && cc < sp && Ip[r * sp + cc] >= 0) act = true;
                }
            lin = tid;
            pw = (i << 16) | j;
        }
        emit(k, act, lin, pw, c_IOFS[k], nullptr);
    }
}

// ---- level-0 conv: 5x5, cin=1 -> 32 ---------------------------------------------
__global__ void conv1_kernel(const float* __restrict__ x, const float* __restrict__ w1) {
    __shared__ float sw[800];
    __shared__ float bsum[32];
    int tid = threadIdx.x;
    for (int t = tid; t < 800; t += 256) sw[t] = w1[t];
    if (tid < 32) bsum[tid] = 0.f;
    __syncthreads();

    int n = min(g_cnt[0], CAP);
    int lane = tid & 31;
    int gw = (blockIdx.x * 256 + tid) >> 5;
    int nw = (gridDim.x * 256) >> 5;
    float pool = 0.f;
    for (int p = gw; p < n; p += nw) {
        int pw = g_pos[p];
        int i = pw >> 16, j = pw & 0xffff;
        float acc = 0.f;
        #pragma unroll
        for (int dy = 0; dy < 5; dy++) {
            int r = i + dy - 2;
            if ((unsigned)r < 2048u) {
                #pragma unroll
                for (int dx = 0; dx < 5; dx++) {
                    int cc = j + dx - 2;
                    if ((unsigned)cc < 2048u)
                        acc = fmaf(x[r * 2048 + cc], sw[(dy * 5 + dx) * 32 + lane], acc);
                }
            }
        }
        acc = fmaxf(acc, 0.f);
        g_FA[(size_t)p * 32 + lane] = acc;
        pool += acc;
    }
    atomicAdd(&bsum[lane], pool);
    __syncthreads();
    if (tid < 32) atomicAdd(&g_pools[tid], bsum[tid]);
}

// ---- levels 1..7: reg-resident sparse conv ---------------------------------------
// 256 threads/block; thread = 1 position x 16 channels; tile = 128 positions.
// Weights in 128B-aligned smem (warp reads land in one 128B window per ci).
// No __syncthreads in the tile loop; warp-uniform tap skip via ballot.
__global__ __launch_bounds__(256) void convk_kernel(const float* __restrict__ ws,
                                                    int level, int sprev, int iofs_prev) {
    __shared__ __align__(128) float sW[9216];   // [tap][ci][co]
    __shared__ float spool[32];
    const float* __restrict__ Fprev = (level & 1) ? g_FA : g_FB;
    float* __restrict__ Fcur = (level & 1) ? g_FB : g_FA;
    int tid = threadIdx.x;
    {
        const float4* src = (const float4*)(ws + (size_t)(level - 1) * 9216);
        float4* dst = (float4*)sW;
        #pragma unroll
        for (int t = 0; t < 9; t++) dst[tid + t * 256] = src[tid + t * 256];
    }
    if (tid < 32) spool[tid] = 0.f;
    __syncthreads();

    int n = min(g_cnt[level], CAP);
    const int* __restrict__ posl = g_pos + level * CAP;
    const int* __restrict__ Iprev = g_idx + iofs_prev;

    int half = tid & 1;           // 0: ch 0..15, 1: ch 16..31
    int chb  = half * 16;
    int pid  = tid >> 1;          // 0..127 position within tile

    unsigned long long pool[8];
    #pragma unroll
    for (int i = 0; i < 8; i++) pool[i] = 0ull;

    for (int base = blockIdx.x * 128; base < n; base += gridDim.x * 128) {
        int p = base + pid;
        int pw = (p < n) ? posl[p] : -1;
        int nb[9];
        #pragma unroll
        for (int d = 0; d < 9; d++) {
            int a = -1;
            if (pw >= 0) {
                int r = 2 * (pw >> 16) + d / 3 - 1;
                int c = 2 * (pw & 0xffff) + d % 3 - 1;
                if ((unsigned)r < (unsigned)sprev && (unsigned)c < (unsigned)sprev)
                    a = Iprev[r * sprev + c];
            }
            nb[d] = a;
        }
        unsigned long long acc[8];
        #pragma unroll
        for (int i = 0; i < 8; i++) acc[i] = 0ull;

        #pragma unroll 1
        for (int d = 0; d < 9; d++) {
            bool v = nb[d] >= 0;
            if (!__ballot_sync(0xffffffffu, v)) continue;    // warp-uniform skip
            const float* ap = Fprev + (size_t)max(nb[d], 0) * 32;
            const float* wd = sW + d * 1024 + chb;           // this half's 16 ch
            #pragma unroll
            for (int q = 0; q < 8; q++) {
                float4 x = v ? *(const float4*)(ap + q * 4)
                             : make_float4(0.f, 0.f, 0.f, 0.f);
                #pragma unroll
                for (int j = 0; j < 4; j++) {
                    int ci = q * 4 + j;
                    float e = (j == 0) ? x.x : (j == 1) ? x.y : (j == 2) ? x.z : x.w;
                    unsigned long long A;
                    PACK_DUP(A, e);
                    const ulonglong2* w2 = (const ulonglong2*)(wd + ci * 32);
                    ulonglong2 wa = w2[0];                   // ch pairs 0..3
                    ulonglong2 wb = w2[1];                   // ch pairs 4..7
                    FMA2(acc[0], A, wa.x, acc[0]);
                    FMA2(acc[1], A, wa.y, acc[1]);
                    FMA2(acc[2], A, wb.x, acc[2]);
                    FMA2(acc[3], A, wb.y, acc[3]);
                    FMA2(acc[4], A, w2[2].x, acc[4]);
                    FMA2(acc[5], A, w2[2].y, acc[5]);
                    FMA2(acc[6], A, w2[3].x, acc[6]);
                    FMA2(acc[7], A, w2[3].y, acc[7]);
                }
            }
        }

        // epilogue: relu (packed), pool, store 16 channels
        #pragma unroll
        for (int i = 0; i < 8; i++) {
            float2 f = upk(acc[i]);
            f.x = fmaxf(f.x, 0.f); f.y = fmaxf(f.y, 0.f);
            unsigned long long P;
            asm("mov.b64 %0, {%1, %2};" : "=l"(P)
                : "r"(__float_as_uint(f.x)), "r"(__float_as_uint(f.y)));
            ADD2(pool[i], P, pool[i]);
            acc[i] = P;
        }
        if (p < n) {
            ulonglong2* dst = (ulonglong2*)(Fcur + (size_t)p * 32 + chb);
            dst[0] = make_ulonglong2(acc[0], acc[1]);
            dst[1] = make_ulonglong2(acc[2], acc[3]);
            dst[2] = make_ulonglong2(acc[4], acc[5]);
            dst[3] = make_ulonglong2(acc[6], acc[7]);
        }
    }

    // pool reduce: parity-preserving butterfly (offsets 2..16), lanes 0/1 commit
    #pragma unroll
    for (int i = 0; i < 8; i++) {
        #pragma unroll
        for (int off = 16; off >= 2; off >>= 1) {
            unsigned long long o = __shfl_xor_sync(0xffffffffu, pool[i], off);
            ADD2(pool[i], o, pool[i]);
        }
    }
    if ((tid & 31) < 2) {
        #pragma unroll
        for (int i = 0; i < 8; i++) {
            float2 f = upk(pool[i]);
            atomicAdd(&spool[chb + 2 * i],     f.x);
            atomicAdd(&spool[chb + 2 * i + 1], f.y);
        }
    }
    __syncthreads();
    if (tid < 32) atomicAdd(&g_pools[level * 32 + tid], spool[tid]);
}

// ---- tail: levels 8..13 + MLP + re-zero state (1 block) --------------------------
__global__ __launch_bounds__(256) void tail_kernel(
    const float* __restrict__ ws,
    const float* __restrict__ wm1, const float* __restrict__ bm1,
    const float* __restrict__ wm2, const float* __restrict__ bm2,
    float* __restrict__ out) {
    __shared__ float spool[32];
    int tid = threadIdx.x, wid = tid >> 5, lane = tid & 31;

    for (int k = 8; k < NLEV; k++) {
        int n = min(g_cnt[k], CAP);
        int sp = c_LS[k - 1];
        const int* Ip = g_idx + c_IOFS[k - 1];
        const float* Fp = (k & 1) ? g_FA : g_FB;
        float* Fc = (k & 1) ? g_FB : g_FA;
        const float* W = ws + (size_t)(k - 1) * 9216;
        if (tid < 32) spool[tid] = 0.f;
        __syncthreads();
        float pool = 0.f;
        for (int p = wid; p < n; p += 8) {
            int pw = g_pos[k * CAP + p];
            int pi = pw >> 16, pj = pw & 0xffff;
            float acc = 0.f;
            for (int d = 0; d < 9; d++) {
                int r = 2 * pi + d / 3 - 1;
                int cc = 2 * pj + d % 3 - 1;
                if ((unsigned)r < (unsigned)sp && (unsigned)cc < (unsigned)sp) {
                    int nbv = Ip[r * sp + cc];
                    if (nbv >= 0) {
                        float row = Fp[(size_t)nbv * 32 + lane];
                        const float* wd = W + d * 1024;
                        #pragma unroll
                        for (int ci = 0; ci < 32; ci++)
                            acc = fmaf(__shfl_sync(0xffffffffu, row, ci),
                                       wd[ci * 32 + lane], acc);
                    }
                }
            }
            acc = fmaxf(acc, 0.f);
            Fc[(size_t)p * 32 + lane] = acc;
            pool += acc;
        }
        atomicAdd(&spool[lane], pool);
        __syncthreads();
        if (tid < 32) g_pools[k * 32 + tid] = spool[tid];
        __syncthreads();
    }

    __shared__ float sf[448];
    __shared__ float sh[256];
    for (int i = tid; i < 448; i += 256) {
        int k = i >> 5;
        float cnt = (float)max(g_cnt[k], 1);
        sf[i] = g_pools[i] / cnt;
    }
    __syncthreads();
    {
        float acc = bm1[tid];
        #pragma unroll 4
        for (int i = 0; i < 448; i++) acc = fmaf(sf[i], wm1[i * 256 + tid], acc);
        sh[tid] = fmaxf(acc, 0.f);
    }
    __syncthreads();
    if (tid < 128) {
        float acc = bm2[tid];
        #pragma unroll 4
        for (int j = 0; j < 256; j++) acc = fmaf(sh[j], wm2[j * 128 + tid], acc);
        out[tid] = acc;
    }

    // re-zero state so the next graph replay starts clean
    __syncthreads();
    for (int i = tid; i < NLEV * 32; i += 256) g_pools[i] = 0.f;
    if (tid < NLEV) g_cnt[tid] = 0;
}

// ---- host launch --------------------------------------------------------------------
static const int H_LS[NLEV]   = {2048,1024,512,256,128,64,32,16,8,4,2,1,1,1};
static const int H_IOFS[NLEV] = {0,4194304,5242880,5505024,5570560,5586944,5591040,
                                 5592064,5592320,5592384,5592400,5592404,5592405,5592406};

extern "C" void kernel_launch(void* const* d_in, const int* in_sizes, int n_in,
                              void* d_out, int out_size) {
    const float* x    = (const float*)d_in[0];
    const float* mask = (const float*)d_in[1];
    const float* w1   = (const float*)d_in[2];
    const float* ws   = (const float*)d_in[3];
    const float* wm1  = (const float*)d_in[4];
    const float* bm1  = (const float*)d_in[5];
    const float* wm2  = (const float*)d_in[6];
    const float* bm2  = (const float*)d_in[7];
    float* out = (float*)d_out;

    build_all0<<<256, 1024>>>(mask);
    build_top<<<1, 1024>>>();
    conv1_kernel<<<2048, 256>>>(x, w1);

    // 128-position tiles; stride loop handles overflow beyond these grids
    static const int cgrid[8] = {0, 324, 308, 246, 120, 32, 8, 2};
    for (int k = 1; k <= 7; k++)
        convk_kernel<<<cgrid[k], 256>>>(ws, k, H_LS[k - 1], H_IOFS[k - 1]);

    tail_kernel<<<1, 256>>>(ws, wm1, bm1, wm2, bm2, out);
}

// round 9
// speedup vs baseline: 1.6161x; 1.0775x over previous
#include <cuda_runtime.h>
#include <cstdint>
#include <cstring>

// ============================================================================
// Sparse masked CNN pyramid (14 levels) + MLP head — round 9.
// TWO kernels total:
//   build_all0  : mask pyramid L0..7 (256x1024) + zero barrier counters
//   main_kernel : persistent (grid-wide spin barriers, per-epoch counters):
//                 phase0 conv1 + build_top(L8..13), then convk L1..7
//                 (thread = 1 pos x 8 ch), then block0: tail L8..13 + MLP.
// Barrier counters are zeroed by the NEXT replay's build_all0 (no reset race).
// Cross-phase feature reads use __ldcg (L1 is stale across phases).
// ============================================================================

#define CAP 131072
#define NLEV 14
#define IDX_TOTAL 5592407

__device__ __align__(16) float g_FA[CAP * 32];
__device__ __align__(16) float g_FB[CAP * 32];
__device__ int   g_idx[IDX_TOTAL];
__device__ int   g_pos[NLEV * CAP];
__device__ int   g_cnt[NLEV];              // zero-init; main block0 re-zeroes
__device__ float g_pools[NLEV * 32];       // zero-init; main block0 re-zeroes
__device__ volatile unsigned g_bars[16];   // zero-init; build_all0 re-zeroes

__constant__ int c_LS[NLEV]   = {2048,1024,512,256,128,64,32,16,8,4,2,1,1,1};
__constant__ int c_IOFS[NLEV] = {0,4194304,5242880,5505024,5570560,5586944,5591040,
                                 5592064,5592320,5592384,5592400,5592404,5592405,5592406};

#define FMA2(d, a, b, c) \
    asm("fma.rn.f32x2 %0, %1, %2, %3;" : "=l"(d) : "l"(a), "l"(b), "l"(c))
#define ADD2(d, a, b) \
    asm("add.rn.f32x2 %0, %1, %2;" : "=l"(d) : "l"(a), "l"(b))
#define PACK_DUP(d, a) \
    do { unsigned _u = __float_as_uint(a); \
         asm("mov.b64 %0, {%1, %1};" : "=l"(d) : "r"(_u)); } while (0)

__device__ __forceinline__ float2 upk(unsigned long long a) {
    float2 f; memcpy(&f, &a, 8); return f;
}

// ---- grid-wide barriers (per-epoch counters; never reset inside main) --------
__device__ __forceinline__ void gwait(int e, unsigned nb) {
    __syncthreads();
    if (threadIdx.x == 0) {
        __threadfence();
        atomicAdd((unsigned*)&g_bars[e], 1u);
        while (g_bars[e] < nb) __nanosleep(128);
        __threadfence();
    }
    __syncthreads();
}
__device__ __forceinline__ void garrive(int e) {
    __syncthreads();
    __threadfence();
    if (threadIdx.x == 0) atomicAdd((unsigned*)&g_bars[e], 1u);
}

// ---- block compaction step (1024-thread blocks only) -------------------------
__device__ __forceinline__ void emit(int level, bool act, int lin, int posword,
                                     int iofs, unsigned* bitdst) {
    __shared__ int ewcnt[32];
    __shared__ int ewbase[32];
    __shared__ int ebbase;
    int tid = threadIdx.x, wid = tid >> 5, lane = tid & 31;
    unsigned m = __ballot_sync(0xffffffffu, act);
    if (lane == 0) {
        ewcnt[wid] = __popc(m);
        if (bitdst) bitdst[wid] = m;
    }
    __syncthreads();
    if (tid < 32) {
        int cc = ewcnt[tid];
        int x = cc;
        #pragma unroll
        for (int o = 1; o < 32; o <<= 1) {
            int y = __shfl_up_sync(0xffffffffu, x, o);
            if (tid >= o) x += y;
        }
        ewbase[tid] = x - cc;
        if (tid == 31) ebbase = atomicAdd(&g_cnt[level], x);
    }
    __syncthreads();
    int idx = -1;
    if (act) {
        idx = ebbase + ewbase[wid] + __popc(m & ((1u << lane) - 1u));
        if (idx < CAP) g_pos[level * CAP + idx] = posword;
        else idx = -1;
    }
    if (lin >= 0) g_idx[iofs + lin] = idx;
    __syncthreads();
}

__device__ __forceinline__ int getbit(const unsigned* a, int c) {
    return (a[c >> 5] >> (c & 31)) & 1;
}

// ---- build: levels 0..7, block = 128x128 base tile; zero barrier counters ----
__global__ __launch_bounds__(1024) void build_all0(const float* __restrict__ mask) {
    if (blockIdx.x == 0 && threadIdx.x < 16) g_bars[threadIdx.x] = 0;

    __shared__ unsigned a0[512];
    __shared__ unsigned a1[128];
    __shared__ unsigned a2[32];
    __shared__ unsigned a3[8];
    __shared__ unsigned a4[32];
    __shared__ unsigned a5[32];
    __shared__ unsigned a6[32];
    int tid = threadIdx.x;
    int tx = blockIdx.x & 15, ty = blockIdx.x >> 4;

    for (int r = 0; r < 16; r++) {
        int c = r * 1024 + tid;
        int li = c >> 7, lj = c & 127;
        int i = ty * 128 + li, j = tx * 128 + lj;
        bool act = (mask[i * 2048 + j] != 0.0f);
        emit(0, act, i * 2048 + j, (i << 16) | j, c_IOFS[0], a0 + r * 32);
    }
    unsigned* bits[8] = {a0, a1, a2, a3, a4, a5, a6, nullptr};
    #pragma unroll
    for (int L = 1; L <= 7; L++) {
        int t = 128 >> L;
        int cells = t * t;
        int chunks = (cells + 1023) >> 10;
        int tprev = t * 2;
        for (int r = 0; r < chunks; r++) {
            int c = r * 1024 + tid;
            bool act = false;
            int lin = -1, pw = 0;
            if (c < cells) {
                int li = c / t, lj = c - li * t;
                int c00 = (2 * li) * tprev + 2 * lj;
                const unsigned* pb = bits[L - 1];
                act = getbit(pb, c00) | getbit(pb, c00 + 1) |
                      getbit(pb, c00 + tprev) | getbit(pb, c00 + tprev + 1);
                int i = ty * t + li, j = tx * t + lj;
                lin = i * (2048 >> L) + j;
                pw = (i << 16) | j;
            }
            emit(L, act, lin, pw, c_IOFS[L], (L < 7) ? (bits[L] + r * 32) : nullptr);
        }
    }
}

// ---- persistent main kernel ---------------------------------------------------
__global__ __launch_bounds__(256, 4) void main_kernel(
    const float* __restrict__ x,  const float* __restrict__ w1,
    const float* __restrict__ ws,
    const float* __restrict__ wm1, const float* __restrict__ bm1,
    const float* __restrict__ wm2, const float* __restrict__ bm2,
    float* __restrict__ out) {
    __shared__ __align__(128) float sW[9216];
    __shared__ float spool[32];
    __shared__ unsigned sball[2];
    int tid = threadIdx.x, bid = blockIdx.x;
    int lane = tid & 31;
    unsigned nb_ = gridDim.x;

    // ================= phase 0: conv1 (all blocks) + build_top (last block) ===
    for (int t = tid; t < 800; t += 256) sW[t] = w1[t];
    if (tid < 32) spool[tid] = 0.f;
    __syncthreads();
    {
        int n = min(g_cnt[0], CAP);
        int gw = (bid * 256 + tid) >> 5;
        int nw = (int)nb_ * 8;
        float pl = 0.f;
        for (int p = gw; p < n; p += nw) {
            int pw = g_pos[p];
            int i = pw >> 16, j = pw & 0xffff;
            float acc = 0.f;
            #pragma unroll
            for (int dy = 0; dy < 5; dy++) {
                int r = i + dy - 2;
                bool rv = (unsigned)r < 2048u;
                #pragma unroll
                for (int dx = 0; dx < 5; dx++) {
                    int cc = j + dx - 2;
                    float xv = (rv && (unsigned)cc < 2048u) ? x[r * 2048 + cc] : 0.f;
                    acc = fmaf(xv, sW[(dy * 5 + dx) * 32 + lane], acc);
                }
            }
            acc = fmaxf(acc, 0.f);
            g_FA[(size_t)p * 32 + lane] = acc;
            pl += acc;
        }
        atomicAdd(&spool[lane], pl);
    }
    if (bid == nb_ - 1) {
        // build_top: levels 8..13 (cells <= 64)
        for (int k = 8; k < NLEV; k++) {
            int s = c_LS[k], sp = c_LS[k - 1];
            int cells = s * s;
            const int* Ip = g_idx + c_IOFS[k - 1];
            bool act = false;
            int pwv = 0;
            if (tid < cells) {
                int i = tid / s, j = tid - i * s;
                #pragma unroll
                for (int di = 0; di < 2; di++)
                    #pragma unroll
                    for (int dj = 0; dj < 2; dj++) {
                        int r = 2 * i + di, cc = 2 * j + dj;
                        if (r < sp && cc < sp && __ldcg(&Ip[r * sp + cc]) >= 0)
                            act = true;
                    }
                pwv = (i << 16) | j;
            }
            unsigned m = __ballot_sync(0xffffffffu, act);
            if (tid == 0)  sball[0] = m;
            if (tid == 32) sball[1] = m;
            __syncthreads();
            int cnt0 = __popc(sball[0]);
            int total = cnt0 + (cells > 32 ? __popc(sball[1]) : 0);
            if (tid == 0) g_cnt[k] = total;
            if (tid < cells) {
                int idx = -1;
                if (act) {
                    idx = (tid < 32 ? 0 : cnt0) + __popc(m & ((1u << (tid & 31)) - 1u));
                    g_pos[k * CAP + idx] = pwv;
                }
                g_idx[c_IOFS[k] + tid] = idx;
            }
            __syncthreads();
        }
    }
    __syncthreads();
    if (tid < 32) atomicAdd(&g_pools[tid], spool[tid]);
    __syncthreads();

    // ================= levels 1..7: sparse conv, 1 pos x 8 ch / thread ========
    int pid = tid >> 2;            // 0..63 position within 64-pos tile
    int chb = (tid & 3) * 8;       // 8 output channels
    #pragma unroll 1
    for (int L = 1; L <= 7; L++) {
        {   // stage this level's weights + zero spool (pre-barrier overlap)
            const float4* src = (const float4*)(ws + (size_t)(L - 1) * 9216);
            float4* dst = (float4*)sW;
            #pragma unroll
            for (int t = 0; t < 9; t++) dst[tid + t * 256] = src[tid + t * 256];
        }
        if (tid < 32) spool[tid] = 0.f;
        gwait(L - 1, nb_);         // previous phase complete grid-wide

        const float* __restrict__ Fp = (L & 1) ? g_FA : g_FB;
        float* __restrict__ Fc = (L & 1) ? g_FB : g_FA;
        int sp = c_LS[L - 1];
        const int* __restrict__ Ip = g_idx + c_IOFS[L - 1];
        const int* __restrict__ posl = g_pos + L * CAP;
        int n = min(g_cnt[L], CAP);

        unsigned long long pool[4] = {0ull, 0ull, 0ull, 0ull};
        for (int base = bid * 64; base < n; base += (int)nb_ * 64) {
            int p = base + pid;
            int pw = (p < n) ? posl[p] : -1;
            int pi = pw >> 16, pj = pw & 0xffff;
            unsigned long long acc[4] = {0ull, 0ull, 0ull, 0ull};

            #pragma unroll 1
            for (int d = 0; d < 9; d++) {
                int nbr = -1;
                if (pw >= 0) {
                    int r = 2 * pi + d / 3 - 1;
                    int c = 2 * pj + d % 3 - 1;
                    if ((unsigned)r < (unsigned)sp && (unsigned)c < (unsigned)sp)
                        nbr = Ip[r * sp + c];
                }
                bool v = nbr >= 0;
                if (!__ballot_sync(0xffffffffu, v)) continue;   // warp tap skip
                const float* ap = Fp + (size_t)max(nbr, 0) * 32;
                const float* wd = sW + d * 1024 + chb;
                #pragma unroll
                for (int q = 0; q < 8; q++) {
                    float4 xq = v ? __ldcg((const float4*)(ap + q * 4))
                                  : make_float4(0.f, 0.f, 0.f, 0.f);
                    #pragma unroll
                    for (int j2 = 0; j2 < 4; j2++) {
                        float e = (j2 == 0) ? xq.x : (j2 == 1) ? xq.y
                                : (j2 == 2) ? xq.z : xq.w;
                        unsigned long long A;
                        PACK_DUP(A, e);
                        const ulonglong2* w2 =
                            (const ulonglong2*)(wd + (q * 4 + j2) * 32);
                        ulonglong2 wa = w2[0];
                        ulonglong2 wb = w2[1];
                        FMA2(acc[0], A, wa.x, acc[0]);
                        FMA2(acc[1], A, wa.y, acc[1]);
                        FMA2(acc[2], A, wb.x, acc[2]);
                        FMA2(acc[3], A, wb.y, acc[3]);
                    }
                }
            }
            // relu (packed), pool, store 8 channels
            #pragma unroll
            for (int i2 = 0; i2 < 4; i2++) {
                float2 f = upk(acc[i2]);
                f.x = fmaxf(f.x, 0.f); f.y = fmaxf(f.y, 0.f);
                unsigned long long P;
                asm("mov.b64 %0, {%1, %2};" : "=l"(P)
                    : "r"(__float_as_uint(f.x)), "r"(__float_as_uint(f.y)));
                ADD2(pool[i2], P, pool[i2]);
                acc[i2] = P;
            }
            if (p < n) {
                ulonglong2* dst = (ulonglong2*)(Fc + (size_t)p * 32 + chb);
                dst[0] = make_ulonglong2(acc[0], acc[1]);
                dst[1] = make_ulonglong2(acc[2], acc[3]);
            }
        }
        // pool: butterfly (offsets 16,8,4 preserve lane&3 channel groups)
        #pragma unroll
        for (int i2 = 0; i2 < 4; i2++) {
            #pragma unroll
            for (int off = 16; off >= 4; off >>= 1) {
                unsigned long long o = __shfl_xor_sync(0xffffffffu, pool[i2], off);
                ADD2(pool[i2], o, pool[i2]);
            }
        }
        if (lane < 4) {
            #pragma unroll
            for (int i2 = 0; i2 < 4; i2++) {
                float2 f = upk(pool[i2]);
                atomicAdd(&spool[chb + 2 * i2],     f.x);
                atomicAdd(&spool[chb + 2 * i2 + 1], f.y);
            }
        }
        __syncthreads();
        if (tid < 32) atomicAdd(&g_pools[L * 32 + tid], spool[tid]);
        __syncthreads();
    }

    // ================= tail: block 0 only ======================================
    if (bid != 0) { garrive(7); return; }
    gwait(7, nb_);

    int wid = tid >> 5;
    for (int k = 8; k < NLEV; k++) {
        int n = min(__ldcg(&g_cnt[k]), CAP);
        int sp = c_LS[k - 1];
        const int* Ip = g_idx + c_IOFS[k - 1];
        const float* FpT = (k & 1) ? g_FA : g_FB;
        float* FcT = (k & 1) ? g_FB : g_FA;
        const float* W = ws + (size_t)(k - 1) * 9216;
        if (tid < 32) spool[tid] = 0.f;
        __syncthreads();
        float pl = 0.f;
        for (int p = wid; p < n; p += 8) {
            int pw = __ldcg(&g_pos[k * CAP + p]);
            int pi = pw >> 16, pj = pw & 0xffff;
            float acc = 0.f;
            for (int d = 0; d < 9; d++) {
                int r = 2 * pi + d / 3 - 1;
                int cc = 2 * pj + d % 3 - 1;
                if ((unsigned)r < (unsigned)sp && (unsigned)cc < (unsigned)sp) {
                    int nbv = __ldcg(&Ip[r * sp + cc]);
                    if (nbv >= 0) {
                        float row = __ldcg(&FpT[(size_t)nbv * 32 + lane]);
                        const float* wd = W + d * 1024;
                        #pragma unroll
                        for (int ci = 0; ci < 32; ci++)
                            acc = fmaf(__shfl_sync(0xffffffffu, row, ci),
                                       wd[ci * 32 + lane], acc);
                    }
                }
            }
            acc = fmaxf(acc, 0.f);
            FcT[(size_t)p * 32 + lane] = acc;
            pl += acc;
        }
        atomicAdd(&spool[lane], pl);
        __syncthreads();
        if (tid < 32) g_pools[k * 32 + tid] = spool[tid];
        __syncthreads();
    }

    // MLP: feat[448] -> 256 relu -> 128 (reuse sW as sf/sh)
    float* sf = sW;
    float* sh = sW + 448;
    for (int i = tid; i < 448; i += 256) {
        int k = i >> 5;
        float cnt = (float)max(__ldcg(&g_cnt[k]), 1);
        sf[i] = __ldcg(&g_pools[i]) / cnt;
    }
    __syncthreads();
    {
        float acc = bm1[tid];
        #pragma unroll 4
        for (int i = 0; i < 448; i++) acc = fmaf(sf[i], wm1[i * 256 + tid], acc);
        sh[tid] = fmaxf(acc, 0.f);
    }
    __syncthreads();
    if (tid < 128) {
        float acc = bm2[tid];
        #pragma unroll 4
        for (int j = 0; j < 256; j++) acc = fmaf(sh[j], wm2[j * 128 + tid], acc);
        out[tid] = acc;
    }

    // re-zero state for next replay (barrier counters reset by next build_all0)
    __syncthreads();
    for (int i = tid; i < NLEV * 32; i += 256) g_pools[i] = 0.f;
    if (tid < NLEV) g_cnt[tid] = 0;
}

// ---- host launch ---------------------------------------------------------------
extern "C" void kernel_launch(void* const* d_in, const int* in_sizes, int n_in,
                              void* d_out, int out_size) {
    const float* x    = (const float*)d_in[0];
    const float* mask = (const float*)d_in[1];
    const float* w1   = (const float*)d_in[2];
    const float* ws   = (const float*)d_in[3];
    const float* wm1  = (const float*)d_in[4];
    const float* bm1  = (const float*)d_in[5];
    const float* wm2  = (const float*)d_in[6];
    const float* bm2  = (const float*)d_in[7];
    float* out = (float*)d_out;

    build_all0<<<256, 1024>>>(mask);

    int occ = 0, sms = 0;
    cudaOccupancyMaxActiveBlocksPerMultiprocessor(&occ, main_kernel, 256, 0);
    cudaDeviceGetAttribute(&sms, cudaDevAttrMultiProcessorCount, 0);
    int grid = occ * sms;
    if (grid > 592) grid = 592;
    if (grid < 1) grid = 1;

    main_kernel<<<grid, 256>>>(x, w1, ws, wm1, bm1, wm2, bm2, out);
}